// round 8
// baseline (speedup 1.0000x reference)
#include <cuda_runtime.h>
#include <cuda_fp16.h>
#include <math.h>
#include <stdint.h>

#define BATCH 2
#define SEQ 2048
#define DMODEL 2048
#define NHEAD 16
#define HDIM 128
#define MROWS (BATCH * SEQ)          // 4096
#define ATT_SCALE 0.08838834764831845f  // 1/sqrt(128)

// Scratch (device globals: allocation-free per harness rules)
__device__ __half hx_q[(size_t)MROWS * DMODEL];   // fp16 inputs
__device__ __half hx_k[(size_t)MROWS * DMODEL];
__device__ __half hx_v[(size_t)MROWS * DMODEL];
__device__ __half hw_q[(size_t)DMODEL * DMODEL];  // fp16 weights
__device__ __half hw_k[(size_t)DMODEL * DMODEL];
__device__ __half hw_v[(size_t)DMODEL * DMODEL];
__device__ __half hw_o[(size_t)DMODEL * DMODEL];
__device__ __half h_q[(size_t)MROWS * DMODEL];    // projected q (pre-scaled)
__device__ __half h_k[(size_t)MROWS * DMODEL];
__device__ __half h_v[(size_t)MROWS * DMODEL];
__device__ __half h_a[(size_t)MROWS * DMODEL];    // attention output

// ===========================================================================
// helpers
// ===========================================================================
__device__ __forceinline__ uint32_t smem_u32(const void* p) {
    uint32_t a;
    asm("{ .reg .u64 t; cvta.to.shared.u64 t, %1; cvt.u32.u64 %0, t; }"
        : "=r"(a) : "l"(p));
    return a;
}

__device__ __forceinline__ void cp16(uint32_t dst, const void* src) {
    asm volatile("cp.async.cg.shared.global [%0], [%1], 16;"
                 :: "r"(dst), "l"(src));
}

__device__ __forceinline__ void mma_f16(float* d, const uint32_t* a,
                                        const uint32_t* b)
{
    asm volatile(
        "mma.sync.aligned.m16n8k16.row.col.f32.f16.f16.f32 "
        "{%0,%1,%2,%3}, {%4,%5,%6,%7}, {%8,%9}, {%0,%1,%2,%3};"
        : "+f"(d[0]), "+f"(d[1]), "+f"(d[2]), "+f"(d[3])
        : "r"(a[0]), "r"(a[1]), "r"(a[2]), "r"(a[3]),
          "r"(b[0]), "r"(b[1]));
}

__device__ __forceinline__ void ldsm4(uint32_t* r, uint32_t a) {
    asm volatile("ldmatrix.sync.aligned.m8n8.x4.shared.b16 {%0,%1,%2,%3}, [%4];"
                 : "=r"(r[0]), "=r"(r[1]), "=r"(r[2]), "=r"(r[3]) : "r"(a));
}
__device__ __forceinline__ void ldsm4t(uint32_t* r, uint32_t a) {
    asm volatile("ldmatrix.sync.aligned.m8n8.x4.trans.shared.b16 {%0,%1,%2,%3}, [%4];"
                 : "=r"(r[0]), "=r"(r[1]), "=r"(r[2]), "=r"(r[3]) : "r"(a));
}

__device__ __forceinline__ uint32_t pack_h2(float x, float y) {
    __half2 h = __floats2half2_rn(x, y);
    return *(uint32_t*)&h;
}

// ===========================================================================
// merged fp32 -> fp16 conversion passes
// ===========================================================================
__device__ __forceinline__ uint2 cvt4(float4 v) {
    union { __half2 h[2]; uint2 u; } p;
    p.h[0] = __floats2half2_rn(v.x, v.y);
    p.h[1] = __floats2half2_rn(v.z, v.w);
    return p.u;
}

__global__ void conv_act(const float4* __restrict__ q,
                         const float4* __restrict__ k,
                         const float4* __restrict__ v,
                         uint2* __restrict__ oq, uint2* __restrict__ ok,
                         uint2* __restrict__ ov, int n4)
{
    int i = blockIdx.x * blockDim.x + threadIdx.x;
    if (i >= n4) return;
    const float4* src = (blockIdx.y == 0) ? q : (blockIdx.y == 1) ? k : v;
    uint2* dst = (blockIdx.y == 0) ? oq : (blockIdx.y == 1) ? ok : ov;
    dst[i] = cvt4(src[i]);
}

__global__ void conv_w(const float4* __restrict__ w0,
                       const float4* __restrict__ w1,
                       const float4* __restrict__ w2,
                       const float4* __restrict__ w3,
                       uint2* __restrict__ o0, uint2* __restrict__ o1,
                       uint2* __restrict__ o2, uint2* __restrict__ o3, int n4)
{
    int i = blockIdx.x * blockDim.x + threadIdx.x;
    if (i >= n4) return;
    const float4* src = (blockIdx.y == 0) ? w0 : (blockIdx.y == 1) ? w1
                      : (blockIdx.y == 2) ? w2 : w3;
    uint2* dst = (blockIdx.y == 0) ? o0 : (blockIdx.y == 1) ? o1
               : (blockIdx.y == 2) ? o2 : o3;
    dst[i] = cvt4(src[i]);
}

// ===========================================================================
// fp16 mma.sync GEMM core: C[M,2048] = A[M,2048] @ W[2048,2048]^T + bias
// CTA tile 256x256 (halves smem-load ops per MAC), BK=64 halves, 3-stage
// cp.async, 512 threads / 16 warps, warp tile 64x64.
// ===========================================================================
#define TBM 256
#define TBN 256
#define GK 2048
#define GN 2048
#define GBKH 64
#define AP 72
#define ASTGH (TBM * AP)              // 18432 halves
#define BSTGH (TBN * AP)              // 18432 halves
#define STGH (ASTGH + BSTGH)          // 36864 halves
#define GEMM_SMEM (3 * STGH * 2)      // 221184 B
#define NT (GK / GBKH)                // 32

__device__ __forceinline__ void gemm_core(
    const __half* __restrict__ A, const __half* __restrict__ W,
    const float* __restrict__ bias, void* __restrict__ Cout,
    float scale, int half_out, int bx, int by)
{
    extern __shared__ __half gsmh[];

    const int tid = threadIdx.x;
    const int lane = tid & 31;
    const int warp = tid >> 5;        // 0..15
    const int wm = warp & 3;          // 4 m-slots of 64
    const int wn = warp >> 2;         // 4 n-slots of 64
    const int m0 = by * TBM;
    const int n0 = bx * TBN;

    const uint32_t sbase = smem_u32(gsmh);
    const int cr = tid >> 3;          // 0..63
    const int cc = tid & 7;

    float acc[4][8][4];
#pragma unroll
    for (int i = 0; i < 4; i++)
#pragma unroll
        for (int j = 0; j < 8; j++)
#pragma unroll
            for (int r = 0; r < 4; r++) acc[i][j][r] = 0.0f;

    auto issue = [&](int t, int buf) {
        const __half* Ab = A + (size_t)m0 * GK + t * GBKH;
        const __half* Wb = W + (size_t)n0 * GK + t * GBKH;
        const uint32_t sa = sbase + (uint32_t)buf * STGH * 2u;
        const uint32_t sb = sa + ASTGH * 2u;
#pragma unroll
        for (int i = 0; i < 4; i++) {
            const int r = cr + i * 64;
            cp16(sa + (uint32_t)(r * AP + cc * 8) * 2u,
                 Ab + (size_t)r * GK + cc * 8);
            cp16(sb + (uint32_t)(r * AP + cc * 8) * 2u,
                 Wb + (size_t)r * GK + cc * 8);
        }
        asm volatile("cp.async.commit_group;");
    };

    issue(0, 0);
    issue(1, 1);

    // ldmatrix per-lane offsets (bytes)
    const uint32_t a_lane_off =
        (uint32_t)((wm * 64 + (lane & 15)) * AP + ((lane >> 4) * 8)) * 2u;
    const uint32_t b_lane_off =
        (uint32_t)((wn * 64 + (lane & 7) + ((lane >> 4) & 1) * 8) * AP
                   + (((lane >> 3) & 1) * 8)) * 2u;

    for (int t = 0; t < NT; ++t) {
        if (t + 1 < NT) {
            asm volatile("cp.async.wait_group 1;");
        } else {
            asm volatile("cp.async.wait_group 0;");
        }
        __syncthreads();
        if (t + 2 < NT) issue(t + 2, (t + 2) % 3);

        const uint32_t sa = sbase + (uint32_t)(t % 3) * STGH * 2u;
        const uint32_t aaddr = sa + a_lane_off;
        const uint32_t baddr = sa + ASTGH * 2u + b_lane_off;

#pragma unroll
        for (int ks = 0; ks < 4; ++ks) {
            uint32_t af[4][4], bf[4][4];
#pragma unroll
            for (int ms = 0; ms < 4; ms++)
                ldsm4(af[ms], aaddr + (uint32_t)(ms * 16 * AP + ks * 16) * 2u);
#pragma unroll
            for (int np = 0; np < 4; np++)
                ldsm4(bf[np], baddr + (uint32_t)(np * 16 * AP + ks * 16) * 2u);
#pragma unroll
            for (int ms = 0; ms < 4; ms++)
#pragma unroll
                for (int np = 0; np < 4; np++) {
                    mma_f16(acc[ms][np * 2], af[ms], bf[np]);
                    mma_f16(acc[ms][np * 2 + 1], af[ms], bf[np] + 2);
                }
        }
    }

    float2 bv[8];
#pragma unroll
    for (int ns = 0; ns < 8; ns++) {
        const int col = n0 + wn * 64 + ns * 8 + 2 * (lane & 3);
        bv[ns] = *(const float2*)(bias + col);
    }

    if (half_out) {
        __half* C = (__half*)Cout;
#pragma unroll
        for (int ms = 0; ms < 4; ms++) {
            const int row0 = m0 + wm * 64 + ms * 16 + (lane >> 2);
#pragma unroll
            for (int ns = 0; ns < 8; ns++) {
                const int col = n0 + wn * 64 + ns * 8 + 2 * (lane & 3);
                __half2 v0 = __floats2half2_rn((acc[ms][ns][0] + bv[ns].x) * scale,
                                               (acc[ms][ns][1] + bv[ns].y) * scale);
                __half2 v1 = __floats2half2_rn((acc[ms][ns][2] + bv[ns].x) * scale,
                                               (acc[ms][ns][3] + bv[ns].y) * scale);
                *(__half2*)(C + (size_t)row0 * GN + col) = v0;
                *(__half2*)(C + (size_t)(row0 + 8) * GN + col) = v1;
            }
        }
    } else {
        float* C = (float*)Cout;
#pragma unroll
        for (int ms = 0; ms < 4; ms++) {
            const int row0 = m0 + wm * 64 + ms * 16 + (lane >> 2);
#pragma unroll
            for (int ns = 0; ns < 8; ns++) {
                const int col = n0 + wn * 64 + ns * 8 + 2 * (lane & 3);
                float2 v0 = make_float2(acc[ms][ns][0] + bv[ns].x,
                                        acc[ms][ns][1] + bv[ns].y);
                float2 v1 = make_float2(acc[ms][ns][2] + bv[ns].x,
                                        acc[ms][ns][3] + bv[ns].y);
                *(float2*)(C + (size_t)row0 * GN + col) = v0;
                *(float2*)(C + (size_t)(row0 + 8) * GN + col) = v1;
            }
        }
    }
}

// fused Q/K/V projection: blockIdx.z selects the stream
__global__ __launch_bounds__(512, 1)
void gemm_qkv(const __half* __restrict__ xq, const __half* __restrict__ xk,
              const __half* __restrict__ xv,
              const __half* __restrict__ wq, const __half* __restrict__ wk,
              const __half* __restrict__ wv,
              const float* __restrict__ bq, const float* __restrict__ bk,
              const float* __restrict__ bv,
              __half* __restrict__ pq, __half* __restrict__ pk,
              __half* __restrict__ pv)
{
    const int z = blockIdx.z;
    const __half* A = (z == 0) ? xq : (z == 1) ? xk : xv;
    const __half* W = (z == 0) ? wq : (z == 1) ? wk : wv;
    const float* bias = (z == 0) ? bq : (z == 1) ? bk : bv;
    __half* C = (z == 0) ? pq : (z == 1) ? pk : pv;
    const float scale = (z == 0) ? ATT_SCALE : 1.0f;
    gemm_core(A, W, bias, C, scale, 1, blockIdx.x, blockIdx.y);
}

__global__ __launch_bounds__(512, 1)
void gemm_one(const __half* __restrict__ A, const __half* __restrict__ W,
              const float* __restrict__ bias, void* __restrict__ Cout,
              float scale, int half_out)
{
    gemm_core(A, W, bias, Cout, scale, half_out, blockIdx.x, blockIdx.y);
}

// ===========================================================================
// fp16 flash attention v2 (unchanged from R7): register P, ldsm x4.
// ===========================================================================
#define FP 136
#define TILE_H (128 * FP)
#define FLASH_SMEM (TILE_H * 2 * 5)   // 174080 B

__global__ __launch_bounds__(256, 1)
void flash_tc(const __half* __restrict__ Q, const __half* __restrict__ K,
              const __half* __restrict__ V, __half* __restrict__ O)
{
    extern __shared__ __half fsmh[];

    const int qt = (SEQ / 128) - 1 - blockIdx.x;
    const int h = blockIdx.y;
    const int b = blockIdx.z;
    const int q0 = qt * 128;
    const size_t headoff = (size_t)b * SEQ * DMODEL + (size_t)h * HDIM;
    const __half* Qb = Q + headoff;
    const __half* Kb = K + headoff;
    const __half* Vb = V + headoff;

    const int tid = threadIdx.x;
    const int lane = tid & 31;
    const int warp = tid >> 5;
    const int g = lane >> 2;
    const int q4 = lane & 3;

    const uint32_t sQ = smem_u32(fsmh);
    const uint32_t sK0 = sQ + TILE_H * 2u;
    const uint32_t sV0 = sQ + 3u * TILE_H * 2u;

#pragma unroll
    for (int i = 0; i < 8; ++i) {
        const int slot = tid + i * 256;
        const int r = slot >> 4, c = slot & 15;
        cp16(sQ + (uint32_t)(r * FP + c * 8) * 2u,
             Qb + (size_t)(q0 + r) * DMODEL + c * 8);
    }

    auto issue_kv = [&](int kt) {
        const int buf = kt & 1;
        const int k0 = kt * 128;
        const uint32_t dK = sK0 + (uint32_t)buf * TILE_H * 2u;
        const uint32_t dV = sV0 + (uint32_t)buf * TILE_H * 2u;
#pragma unroll
        for (int i = 0; i < 8; ++i) {
            const int slot = tid + i * 256;
            const int r = slot >> 4, c = slot & 15;
            cp16(dK + (uint32_t)(r * FP + c * 8) * 2u,
                 Kb + (size_t)(k0 + r) * DMODEL + c * 8);
            cp16(dV + (uint32_t)(r * FP + c * 8) * 2u,
                 Vb + (size_t)(k0 + r) * DMODEL + c * 8);
        }
        asm volatile("cp.async.commit_group;");
    };

    issue_kv(0);
    if (qt > 0) issue_kv(1);

    float m0 = -INFINITY, m1 = -INFINITY, l0 = 0.0f, l1 = 0.0f;
    float acco[16][4];
#pragma unroll
    for (int j = 0; j < 16; j++)
#pragma unroll
        for (int r = 0; r < 4; r++) acco[j][r] = 0.0f;

    const int ar = warp * 16 + g;

    const uint32_t qa_off =
        (uint32_t)((warp * 16 + (lane & 15)) * FP + ((lane >> 4) * 8)) * 2u;
    const uint32_t kb4_off =
        (uint32_t)(((lane & 7) + ((lane >> 4) & 1) * 8) * FP
                   + (((lane >> 3) & 1) * 8)) * 2u;
    const uint32_t vt4_off =
        (uint32_t)(((lane & 7) + ((lane >> 3) & 1) * 8) * FP
                   + ((lane >> 4) * 8)) * 2u;

    uint32_t qf[8][4];
    bool qloaded = false;

    for (int kt = 0; kt <= qt; ++kt) {
        const int buf = kt & 1;
        const uint32_t sKc = sK0 + (uint32_t)buf * TILE_H * 2u;
        const uint32_t sVc = sV0 + (uint32_t)buf * TILE_H * 2u;

        if (kt < qt) {
            asm volatile("cp.async.wait_group 1;");
        } else {
            asm volatile("cp.async.wait_group 0;");
        }
        __syncthreads();

        if (!qloaded) {
#pragma unroll
            for (int ks = 0; ks < 8; ++ks)
                ldsm4(qf[ks], sQ + qa_off + (uint32_t)(ks * 16) * 2u);
            qloaded = true;
        }

        float accs[16][4];
#pragma unroll
        for (int j = 0; j < 16; j++)
#pragma unroll
            for (int r = 0; r < 4; r++) accs[j][r] = 0.0f;

#pragma unroll
        for (int ks = 0; ks < 8; ++ks) {
#pragma unroll
            for (int jp = 0; jp < 8; ++jp) {
                uint32_t bb[4];
                ldsm4(bb, sKc + kb4_off + (uint32_t)(jp * 16 * FP + ks * 16) * 2u);
                mma_f16(accs[jp * 2], qf[ks], bb);
                mma_f16(accs[jp * 2 + 1], qf[ks], bb + 2);
            }
        }

        if (kt == qt) {
#pragma unroll
            for (int j = 0; j < 16; ++j) {
                const int c0 = j * 8 + 2 * q4;
                if (c0 > ar)          accs[j][0] = -1e30f;
                if (c0 + 1 > ar)      accs[j][1] = -1e30f;
                if (c0 > ar + 8)      accs[j][2] = -1e30f;
                if (c0 + 1 > ar + 8)  accs[j][3] = -1e30f;
            }
        }

        float mx0 = -INFINITY, mx1 = -INFINITY;
#pragma unroll
        for (int j = 0; j < 16; ++j) {
            mx0 = fmaxf(mx0, fmaxf(accs[j][0], accs[j][1]));
            mx1 = fmaxf(mx1, fmaxf(accs[j][2], accs[j][3]));
        }
        mx0 = fmaxf(mx0, __shfl_xor_sync(0xffffffffu, mx0, 1));
        mx0 = fmaxf(mx0, __shfl_xor_sync(0xffffffffu, mx0, 2));
        mx1 = fmaxf(mx1, __shfl_xor_sync(0xffffffffu, mx1, 1));
        mx1 = fmaxf(mx1, __shfl_xor_sync(0xffffffffu, mx1, 2));
        const float mn0 = fmaxf(m0, mx0);
        const float mn1 = fmaxf(m1, mx1);
        const float cr0 = __expf(m0 - mn0);
        const float cr1 = __expf(m1 - mn1);
        float s0 = 0.0f, s1 = 0.0f;
#pragma unroll
        for (int j = 0; j < 16; ++j) {
            accs[j][0] = __expf(accs[j][0] - mn0); s0 += accs[j][0];
            accs[j][1] = __expf(accs[j][1] - mn0); s0 += accs[j][1];
            accs[j][2] = __expf(accs[j][2] - mn1); s1 += accs[j][2];
            accs[j][3] = __expf(accs[j][3] - mn1); s1 += accs[j][3];
        }
        s0 += __shfl_xor_sync(0xffffffffu, s0, 1);
        s0 += __shfl_xor_sync(0xffffffffu, s0, 2);
        s1 += __shfl_xor_sync(0xffffffffu, s1, 1);
        s1 += __shfl_xor_sync(0xffffffffu, s1, 2);
        l0 = l0 * cr0 + s0;  m0 = mn0;
        l1 = l1 * cr1 + s1;  m1 = mn1;
#pragma unroll
        for (int j = 0; j < 16; ++j) {
            acco[j][0] *= cr0; acco[j][1] *= cr0;
            acco[j][2] *= cr1; acco[j][3] *= cr1;
        }

#pragma unroll
        for (int t = 0; t < 8; ++t) {
            uint32_t a[4];
            a[0] = pack_h2(accs[2 * t][0], accs[2 * t][1]);
            a[1] = pack_h2(accs[2 * t][2], accs[2 * t][3]);
            a[2] = pack_h2(accs[2 * t + 1][0], accs[2 * t + 1][1]);
            a[3] = pack_h2(accs[2 * t + 1][2], accs[2 * t + 1][3]);
#pragma unroll
            for (int jp = 0; jp < 8; ++jp) {
                uint32_t bb[4];
                ldsm4t(bb, sVc + vt4_off + (uint32_t)(t * 16 * FP + jp * 16) * 2u);
                mma_f16(acco[jp * 2], a, bb);
                mma_f16(acco[jp * 2 + 1], a, bb + 2);
            }
        }

        __syncthreads();
        if (kt + 2 <= qt) issue_kv(kt + 2);
    }

    const float i0 = 1.0f / l0;
    const float i1 = 1.0f / l1;
#pragma unroll
    for (int j = 0; j < 16; ++j) {
        *(__half2*)(O + headoff + (size_t)(q0 + ar) * DMODEL + j * 8 + 2 * q4) =
            __floats2half2_rn(acco[j][0] * i0, acco[j][1] * i0);
        *(__half2*)(O + headoff + (size_t)(q0 + ar + 8) * DMODEL + j * 8 + 2 * q4) =
            __floats2half2_rn(acco[j][2] * i1, acco[j][3] * i1);
    }
}

// ---------------------------------------------------------------------------
extern "C" void kernel_launch(void* const* d_in, const int* in_sizes, int n_in,
                              void* d_out, int out_size)
{
    const float* query = (const float*)d_in[0];
    const float* key_i = (const float*)d_in[1];
    const float* value = (const float*)d_in[2];
    const float* Wq = (const float*)d_in[3];
    const float* bq = (const float*)d_in[4];
    const float* Wk = (const float*)d_in[5];
    const float* bk = (const float*)d_in[6];
    const float* Wv = (const float*)d_in[7];
    const float* bv = (const float*)d_in[8];
    const float* Wo = (const float*)d_in[9];
    const float* bo = (const float*)d_in[10];
    float* out = (float*)d_out;

    __half *xq, *xk, *xv, *wq, *wk, *wv, *wo, *pq, *pk, *pv, *pa;
    cudaGetSymbolAddress((void**)&xq, hx_q);
    cudaGetSymbolAddress((void**)&xk, hx_k);
    cudaGetSymbolAddress((void**)&xv, hx_v);
    cudaGetSymbolAddress((void**)&wq, hw_q);
    cudaGetSymbolAddress((void**)&wk, hw_k);
    cudaGetSymbolAddress((void**)&wv, hw_v);
    cudaGetSymbolAddress((void**)&wo, hw_o);
    cudaGetSymbolAddress((void**)&pq, h_q);
    cudaGetSymbolAddress((void**)&pk, h_k);
    cudaGetSymbolAddress((void**)&pv, h_v);
    cudaGetSymbolAddress((void**)&pa, h_a);

    const int act4 = (MROWS * DMODEL) / 4;
    const int w4 = (DMODEL * DMODEL) / 4;
    conv_act<<<dim3((act4 + 255) / 256, 3), 256>>>(
        (const float4*)query, (const float4*)key_i, (const float4*)value,
        (uint2*)xq, (uint2*)xk, (uint2*)xv, act4);
    conv_w<<<dim3((w4 + 255) / 256, 4), 256>>>(
        (const float4*)Wq, (const float4*)Wk, (const float4*)Wv,
        (const float4*)Wo, (uint2*)wq, (uint2*)wk, (uint2*)wv, (uint2*)wo, w4);

    cudaFuncSetAttribute(gemm_qkv, cudaFuncAttributeMaxDynamicSharedMemorySize,
                         GEMM_SMEM);
    cudaFuncSetAttribute(gemm_one, cudaFuncAttributeMaxDynamicSharedMemorySize,
                         GEMM_SMEM);

    gemm_qkv<<<dim3(GN / TBN, MROWS / TBM, 3), 512, GEMM_SMEM>>>(
        xq, xk, xv, wq, wk, wv, bq, bk, bv, pq, pk, pv);

    cudaFuncSetAttribute(flash_tc, cudaFuncAttributeMaxDynamicSharedMemorySize,
                         FLASH_SMEM);
    const dim3 agrid(SEQ / 128, NHEAD, BATCH);
    flash_tc<<<agrid, 256, FLASH_SMEM>>>(pq, pk, pv, pa);

    gemm_one<<<dim3(GN / TBN, MROWS / TBM), 512, GEMM_SMEM>>>(
        pa, wo, bo, out, 1.0f, 0);
}

// round 9
// speedup vs baseline: 2.4853x; 2.4853x over previous
#include <cuda_runtime.h>
#include <cuda_fp16.h>
#include <math.h>
#include <stdint.h>

#define BATCH 2
#define SEQ 2048
#define DMODEL 2048
#define NHEAD 16
#define HDIM 128
#define MROWS (BATCH * SEQ)          // 4096
#define ATT_SCALE 0.08838834764831845f  // 1/sqrt(128)
#define LOG2E 1.4426950408889634f

// Scratch (device globals: allocation-free per harness rules)
__device__ __half hx_q[(size_t)MROWS * DMODEL];   // fp16 inputs
__device__ __half hx_k[(size_t)MROWS * DMODEL];
__device__ __half hx_v[(size_t)MROWS * DMODEL];
__device__ __half hw_q[(size_t)DMODEL * DMODEL];  // fp16 weights
__device__ __half hw_k[(size_t)DMODEL * DMODEL];
__device__ __half hw_v[(size_t)DMODEL * DMODEL];
__device__ __half hw_o[(size_t)DMODEL * DMODEL];
__device__ __half h_q[(size_t)MROWS * DMODEL];    // projected q (pre-scaled)
__device__ __half h_k[(size_t)MROWS * DMODEL];
__device__ __half h_v[(size_t)MROWS * DMODEL];
__device__ __half h_a[(size_t)MROWS * DMODEL];    // attention output

// ===========================================================================
// helpers
// ===========================================================================
__device__ __forceinline__ uint32_t smem_u32(const void* p) {
    uint32_t a;
    asm("{ .reg .u64 t; cvta.to.shared.u64 t, %1; cvt.u32.u64 %0, t; }"
        : "=r"(a) : "l"(p));
    return a;
}

__device__ __forceinline__ void cp16(uint32_t dst, const void* src) {
    asm volatile("cp.async.cg.shared.global [%0], [%1], 16;"
                 :: "r"(dst), "l"(src));
}

__device__ __forceinline__ void mma_f16(float* d, const uint32_t* a,
                                        const uint32_t* b)
{
    asm volatile(
        "mma.sync.aligned.m16n8k16.row.col.f32.f16.f16.f32 "
        "{%0,%1,%2,%3}, {%4,%5,%6,%7}, {%8,%9}, {%0,%1,%2,%3};"
        : "+f"(d[0]), "+f"(d[1]), "+f"(d[2]), "+f"(d[3])
        : "r"(a[0]), "r"(a[1]), "r"(a[2]), "r"(a[3]),
          "r"(b[0]), "r"(b[1]));
}

__device__ __forceinline__ void ldsm4(uint32_t* r, uint32_t a) {
    asm volatile("ldmatrix.sync.aligned.m8n8.x4.shared.b16 {%0,%1,%2,%3}, [%4];"
                 : "=r"(r[0]), "=r"(r[1]), "=r"(r[2]), "=r"(r[3]) : "r"(a));
}
__device__ __forceinline__ void ldsm4t(uint32_t* r, uint32_t a) {
    asm volatile("ldmatrix.sync.aligned.m8n8.x4.trans.shared.b16 {%0,%1,%2,%3}, [%4];"
                 : "=r"(r[0]), "=r"(r[1]), "=r"(r[2]), "=r"(r[3]) : "r"(a));
}

__device__ __forceinline__ uint32_t pack_h2(float x, float y) {
    __half2 h = __floats2half2_rn(x, y);
    return *(uint32_t*)&h;
}

// ===========================================================================
// merged fp32 -> fp16 conversion passes
// ===========================================================================
__device__ __forceinline__ uint2 cvt4(float4 v) {
    union { __half2 h[2]; uint2 u; } p;
    p.h[0] = __floats2half2_rn(v.x, v.y);
    p.h[1] = __floats2half2_rn(v.z, v.w);
    return p.u;
}

__global__ void conv_act(const float4* __restrict__ q,
                         const float4* __restrict__ k,
                         const float4* __restrict__ v,
                         uint2* __restrict__ oq, uint2* __restrict__ ok,
                         uint2* __restrict__ ov, int n4)
{
    int i = blockIdx.x * blockDim.x + threadIdx.x;
    if (i >= n4) return;
    const float4* src = (blockIdx.y == 0) ? q : (blockIdx.y == 1) ? k : v;
    uint2* dst = (blockIdx.y == 0) ? oq : (blockIdx.y == 1) ? ok : ov;
    dst[i] = cvt4(src[i]);
}

__global__ void conv_w(const float4* __restrict__ w0,
                       const float4* __restrict__ w1,
                       const float4* __restrict__ w2,
                       const float4* __restrict__ w3,
                       uint2* __restrict__ o0, uint2* __restrict__ o1,
                       uint2* __restrict__ o2, uint2* __restrict__ o3, int n4)
{
    int i = blockIdx.x * blockDim.x + threadIdx.x;
    if (i >= n4) return;
    const float4* src = (blockIdx.y == 0) ? w0 : (blockIdx.y == 1) ? w1
                      : (blockIdx.y == 2) ? w2 : w3;
    uint2* dst = (blockIdx.y == 0) ? o0 : (blockIdx.y == 1) ? o1
               : (blockIdx.y == 2) ? o2 : o3;
    dst[i] = cvt4(src[i]);
}

// ===========================================================================
// fp16 mma.sync GEMM core: C[M,2048] = A[M,2048] @ W[2048,2048]^T + bias
// CTA tile 128x128, 128 threads (4 warps, 2x2 of 64x64), BK=64 halves,
// 3-stage cp.async. smem 110.6KB + regs<200 => 2 CTAs/SM resident.
// ===========================================================================
#define TBM 128
#define TBN 128
#define GK 2048
#define GN 2048
#define GBKH 64
#define AP 72
#define ASTGH (TBM * AP)              // 9216 halves
#define BSTGH (TBN * AP)              // 9216 halves
#define STGH (ASTGH + BSTGH)          // 18432 halves
#define GEMM_SMEM (3 * STGH * 2)      // 110592 B
#define NT (GK / GBKH)                // 32
#define GEMM_THREADS 128

__device__ __forceinline__ void gemm_core(
    const __half* __restrict__ A, const __half* __restrict__ W,
    const float* __restrict__ bias, void* __restrict__ Cout,
    float scale, int half_out, int bx, int by)
{
    extern __shared__ __half gsmh[];

    const int tid = threadIdx.x;
    const int lane = tid & 31;
    const int warp = tid >> 5;        // 0..3
    const int wm = warp & 1;          // 2 m-slots of 64
    const int wn = warp >> 1;         // 2 n-slots of 64
    const int m0 = by * TBM;
    const int n0 = bx * TBN;

    const uint32_t sbase = smem_u32(gsmh);
    const int cr = tid >> 3;          // 0..15
    const int cc = tid & 7;

    float acc[4][8][4];
#pragma unroll
    for (int i = 0; i < 4; i++)
#pragma unroll
        for (int j = 0; j < 8; j++)
#pragma unroll
            for (int r = 0; r < 4; r++) acc[i][j][r] = 0.0f;

    auto issue = [&](int t, int buf) {
        const __half* Ab = A + (size_t)m0 * GK + t * GBKH;
        const __half* Wb = W + (size_t)n0 * GK + t * GBKH;
        const uint32_t sa = sbase + (uint32_t)buf * STGH * 2u;
        const uint32_t sb = sa + ASTGH * 2u;
#pragma unroll
        for (int i = 0; i < 8; i++) {
            const int r = cr + i * 16;
            cp16(sa + (uint32_t)(r * AP + cc * 8) * 2u,
                 Ab + (size_t)r * GK + cc * 8);
            cp16(sb + (uint32_t)(r * AP + cc * 8) * 2u,
                 Wb + (size_t)r * GK + cc * 8);
        }
        asm volatile("cp.async.commit_group;");
    };

    issue(0, 0);
    issue(1, 1);

    // ldmatrix per-lane offsets (bytes)
    const uint32_t a_lane_off =
        (uint32_t)((wm * 64 + (lane & 15)) * AP + ((lane >> 4) * 8)) * 2u;
    const uint32_t b_lane_off =
        (uint32_t)((wn * 64 + (lane & 7) + ((lane >> 4) & 1) * 8) * AP
                   + (((lane >> 3) & 1) * 8)) * 2u;

    for (int t = 0; t < NT; ++t) {
        if (t + 1 < NT) {
            asm volatile("cp.async.wait_group 1;");
        } else {
            asm volatile("cp.async.wait_group 0;");
        }
        __syncthreads();
        if (t + 2 < NT) issue(t + 2, (t + 2) % 3);

        const uint32_t sa = sbase + (uint32_t)(t % 3) * STGH * 2u;
        const uint32_t aaddr = sa + a_lane_off;
        const uint32_t baddr = sa + ASTGH * 2u + b_lane_off;

#pragma unroll
        for (int ks = 0; ks < 4; ++ks) {
            uint32_t af[4][4], bf[4][4];
#pragma unroll
            for (int ms = 0; ms < 4; ms++)
                ldsm4(af[ms], aaddr + (uint32_t)(ms * 16 * AP + ks * 16) * 2u);
#pragma unroll
            for (int np = 0; np < 4; np++)
                ldsm4(bf[np], baddr + (uint32_t)(np * 16 * AP + ks * 16) * 2u);
#pragma unroll
            for (int ms = 0; ms < 4; ms++)
#pragma unroll
                for (int np = 0; np < 4; np++) {
                    mma_f16(acc[ms][np * 2], af[ms], bf[np]);
                    mma_f16(acc[ms][np * 2 + 1], af[ms], bf[np] + 2);
                }
        }
    }

    float2 bv[8];
#pragma unroll
    for (int ns = 0; ns < 8; ns++) {
        const int col = n0 + wn * 64 + ns * 8 + 2 * (lane & 3);
        bv[ns] = *(const float2*)(bias + col);
    }

    if (half_out) {
        __half* C = (__half*)Cout;
#pragma unroll
        for (int ms = 0; ms < 4; ms++) {
            const int row0 = m0 + wm * 64 + ms * 16 + (lane >> 2);
#pragma unroll
            for (int ns = 0; ns < 8; ns++) {
                const int col = n0 + wn * 64 + ns * 8 + 2 * (lane & 3);
                __half2 v0 = __floats2half2_rn((acc[ms][ns][0] + bv[ns].x) * scale,
                                               (acc[ms][ns][1] + bv[ns].y) * scale);
                __half2 v1 = __floats2half2_rn((acc[ms][ns][2] + bv[ns].x) * scale,
                                               (acc[ms][ns][3] + bv[ns].y) * scale);
                *(__half2*)(C + (size_t)row0 * GN + col) = v0;
                *(__half2*)(C + (size_t)(row0 + 8) * GN + col) = v1;
            }
        }
    } else {
        float* C = (float*)Cout;
#pragma unroll
        for (int ms = 0; ms < 4; ms++) {
            const int row0 = m0 + wm * 64 + ms * 16 + (lane >> 2);
#pragma unroll
            for (int ns = 0; ns < 8; ns++) {
                const int col = n0 + wn * 64 + ns * 8 + 2 * (lane & 3);
                float2 v0 = make_float2(acc[ms][ns][0] + bv[ns].x,
                                        acc[ms][ns][1] + bv[ns].y);
                float2 v1 = make_float2(acc[ms][ns][2] + bv[ns].x,
                                        acc[ms][ns][3] + bv[ns].y);
                *(float2*)(C + (size_t)row0 * GN + col) = v0;
                *(float2*)(C + (size_t)(row0 + 8) * GN + col) = v1;
            }
        }
    }
}

// fused Q/K/V projection: blockIdx.z selects the stream
__global__ __launch_bounds__(GEMM_THREADS, 2)
void gemm_qkv(const __half* __restrict__ xq, const __half* __restrict__ xk,
              const __half* __restrict__ xv,
              const __half* __restrict__ wq, const __half* __restrict__ wk,
              const __half* __restrict__ wv,
              const float* __restrict__ bq, const float* __restrict__ bk,
              const float* __restrict__ bv,
              __half* __restrict__ pq, __half* __restrict__ pk,
              __half* __restrict__ pv)
{
    const int z = blockIdx.z;
    const __half* A = (z == 0) ? xq : (z == 1) ? xk : xv;
    const __half* W = (z == 0) ? wq : (z == 1) ? wk : wv;
    const float* bias = (z == 0) ? bq : (z == 1) ? bk : bv;
    __half* C = (z == 0) ? pq : (z == 1) ? pk : pv;
    // q pre-scaled by ATT_SCALE*log2(e) so flash can use exp2
    const float scale = (z == 0) ? (ATT_SCALE * LOG2E) : 1.0f;
    gemm_core(A, W, bias, C, scale, 1, blockIdx.x, blockIdx.y);
}

__global__ __launch_bounds__(GEMM_THREADS, 2)
void gemm_one(const __half* __restrict__ A, const __half* __restrict__ W,
              const float* __restrict__ bias, void* __restrict__ Cout,
              float scale, int half_out)
{
    gemm_core(A, W, bias, Cout, scale, half_out, blockIdx.x, blockIdx.y);
}

// ===========================================================================
// fp16 flash attention v2: register P, ldsm x4, exp2-domain softmax.
// ===========================================================================
#define FP 136
#define TILE_H (128 * FP)
#define FLASH_SMEM (TILE_H * 2 * 5)   // 174080 B

__global__ __launch_bounds__(256, 1)
void flash_tc(const __half* __restrict__ Q, const __half* __restrict__ K,
              const __half* __restrict__ V, __half* __restrict__ O)
{
    extern __shared__ __half fsmh[];

    const int qt = (SEQ / 128) - 1 - blockIdx.x;
    const int h = blockIdx.y;
    const int b = blockIdx.z;
    const int q0 = qt * 128;
    const size_t headoff = (size_t)b * SEQ * DMODEL + (size_t)h * HDIM;
    const __half* Qb = Q + headoff;
    const __half* Kb = K + headoff;
    const __half* Vb = V + headoff;

    const int tid = threadIdx.x;
    const int lane = tid & 31;
    const int warp = tid >> 5;
    const int g = lane >> 2;
    const int q4 = lane & 3;

    const uint32_t sQ = smem_u32(fsmh);
    const uint32_t sK0 = sQ + TILE_H * 2u;
    const uint32_t sV0 = sQ + 3u * TILE_H * 2u;

#pragma unroll
    for (int i = 0; i < 8; ++i) {
        const int slot = tid + i * 256;
        const int r = slot >> 4, c = slot & 15;
        cp16(sQ + (uint32_t)(r * FP + c * 8) * 2u,
             Qb + (size_t)(q0 + r) * DMODEL + c * 8);
    }

    auto issue_kv = [&](int kt) {
        const int buf = kt & 1;
        const int k0 = kt * 128;
        const uint32_t dK = sK0 + (uint32_t)buf * TILE_H * 2u;
        const uint32_t dV = sV0 + (uint32_t)buf * TILE_H * 2u;
#pragma unroll
        for (int i = 0; i < 8; ++i) {
            const int slot = tid + i * 256;
            const int r = slot >> 4, c = slot & 15;
            cp16(dK + (uint32_t)(r * FP + c * 8) * 2u,
                 Kb + (size_t)(k0 + r) * DMODEL + c * 8);
            cp16(dV + (uint32_t)(r * FP + c * 8) * 2u,
                 Vb + (size_t)(k0 + r) * DMODEL + c * 8);
        }
        asm volatile("cp.async.commit_group;");
    };

    issue_kv(0);
    if (qt > 0) issue_kv(1);

    float m0 = -INFINITY, m1 = -INFINITY, l0 = 0.0f, l1 = 0.0f;
    float acco[16][4];
#pragma unroll
    for (int j = 0; j < 16; j++)
#pragma unroll
        for (int r = 0; r < 4; r++) acco[j][r] = 0.0f;

    const int ar = warp * 16 + g;

    const uint32_t qa_off =
        (uint32_t)((warp * 16 + (lane & 15)) * FP + ((lane >> 4) * 8)) * 2u;
    const uint32_t kb4_off =
        (uint32_t)(((lane & 7) + ((lane >> 4) & 1) * 8) * FP
                   + (((lane >> 3) & 1) * 8)) * 2u;
    const uint32_t vt4_off =
        (uint32_t)(((lane & 7) + ((lane >> 3) & 1) * 8) * FP
                   + ((lane >> 4) * 8)) * 2u;

    uint32_t qf[8][4];
    bool qloaded = false;

    for (int kt = 0; kt <= qt; ++kt) {
        const int buf = kt & 1;
        const uint32_t sKc = sK0 + (uint32_t)buf * TILE_H * 2u;
        const uint32_t sVc = sV0 + (uint32_t)buf * TILE_H * 2u;

        if (kt < qt) {
            asm volatile("cp.async.wait_group 1;");
        } else {
            asm volatile("cp.async.wait_group 0;");
        }
        __syncthreads();

        if (!qloaded) {
#pragma unroll
            for (int ks = 0; ks < 8; ++ks)
                ldsm4(qf[ks], sQ + qa_off + (uint32_t)(ks * 16) * 2u);
            qloaded = true;
        }

        float accs[16][4];
#pragma unroll
        for (int j = 0; j < 16; j++)
#pragma unroll
            for (int r = 0; r < 4; r++) accs[j][r] = 0.0f;

#pragma unroll
        for (int ks = 0; ks < 8; ++ks) {
#pragma unroll
            for (int jp = 0; jp < 8; ++jp) {
                uint32_t bb[4];
                ldsm4(bb, sKc + kb4_off + (uint32_t)(jp * 16 * FP + ks * 16) * 2u);
                mma_f16(accs[jp * 2], qf[ks], bb);
                mma_f16(accs[jp * 2 + 1], qf[ks], bb + 2);
            }
        }

        if (kt == qt) {
#pragma unroll
            for (int j = 0; j < 16; ++j) {
                const int c0 = j * 8 + 2 * q4;
                if (c0 > ar)          accs[j][0] = -1e30f;
                if (c0 + 1 > ar)      accs[j][1] = -1e30f;
                if (c0 > ar + 8)      accs[j][2] = -1e30f;
                if (c0 + 1 > ar + 8)  accs[j][3] = -1e30f;
            }
        }

        // online softmax in exp2 domain (log2e folded into Q scale)
        float mx0 = -INFINITY, mx1 = -INFINITY;
#pragma unroll
        for (int j = 0; j < 16; ++j) {
            mx0 = fmaxf(mx0, fmaxf(accs[j][0], accs[j][1]));
            mx1 = fmaxf(mx1, fmaxf(accs[j][2], accs[j][3]));
        }
        mx0 = fmaxf(mx0, __shfl_xor_sync(0xffffffffu, mx0, 1));
        mx0 = fmaxf(mx0, __shfl_xor_sync(0xffffffffu, mx0, 2));
        mx1 = fmaxf(mx1, __shfl_xor_sync(0xffffffffu, mx1, 1));
        mx1 = fmaxf(mx1, __shfl_xor_sync(0xffffffffu, mx1, 2));
        const float mn0 = fmaxf(m0, mx0);
        const float mn1 = fmaxf(m1, mx1);
        const float cr0 = exp2f(m0 - mn0);
        const float cr1 = exp2f(m1 - mn1);
        float s0 = 0.0f, s1 = 0.0f;
#pragma unroll
        for (int j = 0; j < 16; ++j) {
            accs[j][0] = exp2f(accs[j][0] - mn0); s0 += accs[j][0];
            accs[j][1] = exp2f(accs[j][1] - mn0); s0 += accs[j][1];
            accs[j][2] = exp2f(accs[j][2] - mn1); s1 += accs[j][2];
            accs[j][3] = exp2f(accs[j][3] - mn1); s1 += accs[j][3];
        }
        s0 += __shfl_xor_sync(0xffffffffu, s0, 1);
        s0 += __shfl_xor_sync(0xffffffffu, s0, 2);
        s1 += __shfl_xor_sync(0xffffffffu, s1, 1);
        s1 += __shfl_xor_sync(0xffffffffu, s1, 2);
        l0 = l0 * cr0 + s0;  m0 = mn0;
        l1 = l1 * cr1 + s1;  m1 = mn1;
#pragma unroll
        for (int j = 0; j < 16; ++j) {
            acco[j][0] *= cr0; acco[j][1] *= cr0;
            acco[j][2] *= cr1; acco[j][3] *= cr1;
        }

#pragma unroll
        for (int t = 0; t < 8; ++t) {
            uint32_t a[4];
            a[0] = pack_h2(accs[2 * t][0], accs[2 * t][1]);
            a[1] = pack_h2(accs[2 * t][2], accs[2 * t][3]);
            a[2] = pack_h2(accs[2 * t + 1][0], accs[2 * t + 1][1]);
            a[3] = pack_h2(accs[2 * t + 1][2], accs[2 * t + 1][3]);
#pragma unroll
            for (int jp = 0; jp < 8; ++jp) {
                uint32_t bb[4];
                ldsm4t(bb, sVc + vt4_off + (uint32_t)(t * 16 * FP + jp * 16) * 2u);
                mma_f16(acco[jp * 2], a, bb);
                mma_f16(acco[jp * 2 + 1], a, bb + 2);
            }
        }

        __syncthreads();
        if (kt + 2 <= qt) issue_kv(kt + 2);
    }

    const float i0 = 1.0f / l0;
    const float i1 = 1.0f / l1;
#pragma unroll
    for (int j = 0; j < 16; ++j) {
        *(__half2*)(O + headoff + (size_t)(q0 + ar) * DMODEL + j * 8 + 2 * q4) =
            __floats2half2_rn(acco[j][0] * i0, acco[j][1] * i0);
        *(__half2*)(O + headoff + (size_t)(q0 + ar + 8) * DMODEL + j * 8 + 2 * q4) =
            __floats2half2_rn(acco[j][2] * i1, acco[j][3] * i1);
    }
}

// ---------------------------------------------------------------------------
extern "C" void kernel_launch(void* const* d_in, const int* in_sizes, int n_in,
                              void* d_out, int out_size)
{
    const float* query = (const float*)d_in[0];
    const float* key_i = (const float*)d_in[1];
    const float* value = (const float*)d_in[2];
    const float* Wq = (const float*)d_in[3];
    const float* bq = (const float*)d_in[4];
    const float* Wk = (const float*)d_in[5];
    const float* bk = (const float*)d_in[6];
    const float* Wv = (const float*)d_in[7];
    const float* bv = (const float*)d_in[8];
    const float* Wo = (const float*)d_in[9];
    const float* bo = (const float*)d_in[10];
    float* out = (float*)d_out;

    __half *xq, *xk, *xv, *wq, *wk, *wv, *wo, *pq, *pk, *pv, *pa;
    cudaGetSymbolAddress((void**)&xq, hx_q);
    cudaGetSymbolAddress((void**)&xk, hx_k);
    cudaGetSymbolAddress((void**)&xv, hx_v);
    cudaGetSymbolAddress((void**)&wq, hw_q);
    cudaGetSymbolAddress((void**)&wk, hw_k);
    cudaGetSymbolAddress((void**)&wv, hw_v);
    cudaGetSymbolAddress((void**)&wo, hw_o);
    cudaGetSymbolAddress((void**)&pq, h_q);
    cudaGetSymbolAddress((void**)&pk, h_k);
    cudaGetSymbolAddress((void**)&pv, h_v);
    cudaGetSymbolAddress((void**)&pa, h_a);

    const int act4 = (MROWS * DMODEL) / 4;
    const int w4 = (DMODEL * DMODEL) / 4;
    conv_act<<<dim3((act4 + 255) / 256, 3), 256>>>(
        (const float4*)query, (const float4*)key_i, (const float4*)value,
        (uint2*)xq, (uint2*)xk, (uint2*)xv, act4);
    conv_w<<<dim3((w4 + 255) / 256, 4), 256>>>(
        (const float4*)Wq, (const float4*)Wk, (const float4*)Wv,
        (const float4*)Wo, (uint2*)wq, (uint2*)wk, (uint2*)wv, (uint2*)wo, w4);

    cudaFuncSetAttribute(gemm_qkv, cudaFuncAttributeMaxDynamicSharedMemorySize,
                         GEMM_SMEM);
    cudaFuncSetAttribute(gemm_one, cudaFuncAttributeMaxDynamicSharedMemorySize,
                         GEMM_SMEM);

    gemm_qkv<<<dim3(GN / TBN, MROWS / TBM, 3), GEMM_THREADS, GEMM_SMEM>>>(
        xq, xk, xv, wq, wk, wv, bq, bk, bv, pq, pk, pv);

    cudaFuncSetAttribute(flash_tc, cudaFuncAttributeMaxDynamicSharedMemorySize,
                         FLASH_SMEM);
    const dim3 agrid(SEQ / 128, NHEAD, BATCH);
    flash_tc<<<agrid, 256, FLASH_SMEM>>>(pq, pk, pv, pa);

    gemm_one<<<dim3(GN / TBN, MROWS / TBM), GEMM_THREADS, GEMM_SMEM>>>(
        pa, wo, bo, out, 1.0f, 0);
}

// round 10
// speedup vs baseline: 2.4907x; 1.0022x over previous
#include <cuda_runtime.h>
#include <cuda_fp16.h>
#include <math.h>
#include <stdint.h>

#define BATCH 2
#define SEQ 2048
#define DMODEL 2048
#define NHEAD 16
#define HDIM 128
#define MROWS (BATCH * SEQ)          // 4096
#define ATT_SCALE 0.08838834764831845f  // 1/sqrt(128)
#define LOG2E 1.4426950408889634f

// Scratch (device globals: allocation-free per harness rules)
__device__ __half hx_q[(size_t)MROWS * DMODEL];   // fp16 inputs
__device__ __half hx_k[(size_t)MROWS * DMODEL];
__device__ __half hx_v[(size_t)MROWS * DMODEL];
__device__ __half hw_q[(size_t)DMODEL * DMODEL];  // fp16 weights
__device__ __half hw_k[(size_t)DMODEL * DMODEL];
__device__ __half hw_v[(size_t)DMODEL * DMODEL];
__device__ __half hw_o[(size_t)DMODEL * DMODEL];
__device__ __half h_q[(size_t)MROWS * DMODEL];    // projected q (pre-scaled)
__device__ __half h_k[(size_t)MROWS * DMODEL];
__device__ __half h_v[(size_t)MROWS * DMODEL];
__device__ __half h_a[(size_t)MROWS * DMODEL];    // attention output

// ===========================================================================
// helpers
// ===========================================================================
__device__ __forceinline__ uint32_t smem_u32(const void* p) {
    uint32_t a;
    asm("{ .reg .u64 t; cvta.to.shared.u64 t, %1; cvt.u32.u64 %0, t; }"
        : "=r"(a) : "l"(p));
    return a;
}

__device__ __forceinline__ void cp16(uint32_t dst, const void* src) {
    asm volatile("cp.async.cg.shared.global [%0], [%1], 16;"
                 :: "r"(dst), "l"(src));
}

__device__ __forceinline__ void mma_f16(float* d, const uint32_t* a,
                                        const uint32_t* b)
{
    asm volatile(
        "mma.sync.aligned.m16n8k16.row.col.f32.f16.f16.f32 "
        "{%0,%1,%2,%3}, {%4,%5,%6,%7}, {%8,%9}, {%0,%1,%2,%3};"
        : "+f"(d[0]), "+f"(d[1]), "+f"(d[2]), "+f"(d[3])
        : "r"(a[0]), "r"(a[1]), "r"(a[2]), "r"(a[3]),
          "r"(b[0]), "r"(b[1]));
}

__device__ __forceinline__ void ldsm4(uint32_t* r, uint32_t a) {
    asm volatile("ldmatrix.sync.aligned.m8n8.x4.shared.b16 {%0,%1,%2,%3}, [%4];"
                 : "=r"(r[0]), "=r"(r[1]), "=r"(r[2]), "=r"(r[3]) : "r"(a));
}
__device__ __forceinline__ void ldsm4t(uint32_t* r, uint32_t a) {
    asm volatile("ldmatrix.sync.aligned.m8n8.x4.trans.shared.b16 {%0,%1,%2,%3}, [%4];"
                 : "=r"(r[0]), "=r"(r[1]), "=r"(r[2]), "=r"(r[3]) : "r"(a));
}

__device__ __forceinline__ uint32_t pack_h2(float x, float y) {
    __half2 h = __floats2half2_rn(x, y);
    return *(uint32_t*)&h;
}

// ===========================================================================
// merged fp32 -> fp16 conversion passes
// ===========================================================================
__device__ __forceinline__ uint2 cvt4(float4 v) {
    union { __half2 h[2]; uint2 u; } p;
    p.h[0] = __floats2half2_rn(v.x, v.y);
    p.h[1] = __floats2half2_rn(v.z, v.w);
    return p.u;
}

__global__ void conv_act(const float4* __restrict__ q,
                         const float4* __restrict__ k,
                         const float4* __restrict__ v,
                         uint2* __restrict__ oq, uint2* __restrict__ ok,
                         uint2* __restrict__ ov, int n4)
{
    int i = blockIdx.x * blockDim.x + threadIdx.x;
    if (i >= n4) return;
    const float4* src = (blockIdx.y == 0) ? q : (blockIdx.y == 1) ? k : v;
    uint2* dst = (blockIdx.y == 0) ? oq : (blockIdx.y == 1) ? ok : ov;
    dst[i] = cvt4(src[i]);
}

__global__ void conv_w(const float4* __restrict__ w0,
                       const float4* __restrict__ w1,
                       const float4* __restrict__ w2,
                       const float4* __restrict__ w3,
                       uint2* __restrict__ o0, uint2* __restrict__ o1,
                       uint2* __restrict__ o2, uint2* __restrict__ o3, int n4)
{
    int i = blockIdx.x * blockDim.x + threadIdx.x;
    if (i >= n4) return;
    const float4* src = (blockIdx.y == 0) ? w0 : (blockIdx.y == 1) ? w1
                      : (blockIdx.y == 2) ? w2 : w3;
    uint2* dst = (blockIdx.y == 0) ? o0 : (blockIdx.y == 1) ? o1
               : (blockIdx.y == 2) ? o2 : o3;
    dst[i] = cvt4(src[i]);
}

// ===========================================================================
// fp16 mma.sync GEMM core (unchanged from R9 win): CTA 128x128, 128 threads,
// 4 warps (2x2 of 64x64), BK=64, 3-stage cp.async, 2 CTAs/SM.
// ===========================================================================
#define TBM 128
#define TBN 128
#define GK 2048
#define GN 2048
#define GBKH 64
#define AP 72
#define ASTGH (TBM * AP)
#define BSTGH (TBN * AP)
#define STGH (ASTGH + BSTGH)
#define GEMM_SMEM (3 * STGH * 2)      // 110592 B
#define NT (GK / GBKH)                // 32
#define GEMM_THREADS 128

__device__ __forceinline__ void gemm_core(
    const __half* __restrict__ A, const __half* __restrict__ W,
    const float* __restrict__ bias, void* __restrict__ Cout,
    float scale, int half_out, int bx, int by)
{
    extern __shared__ __half gsmh[];

    const int tid = threadIdx.x;
    const int lane = tid & 31;
    const int warp = tid >> 5;
    const int wm = warp & 1;
    const int wn = warp >> 1;
    const int m0 = by * TBM;
    const int n0 = bx * TBN;

    const uint32_t sbase = smem_u32(gsmh);
    const int cr = tid >> 3;
    const int cc = tid & 7;

    float acc[4][8][4];
#pragma unroll
    for (int i = 0; i < 4; i++)
#pragma unroll
        for (int j = 0; j < 8; j++)
#pragma unroll
            for (int r = 0; r < 4; r++) acc[i][j][r] = 0.0f;

    auto issue = [&](int t, int buf) {
        const __half* Ab = A + (size_t)m0 * GK + t * GBKH;
        const __half* Wb = W + (size_t)n0 * GK + t * GBKH;
        const uint32_t sa = sbase + (uint32_t)buf * STGH * 2u;
        const uint32_t sb = sa + ASTGH * 2u;
#pragma unroll
        for (int i = 0; i < 8; i++) {
            const int r = cr + i * 16;
            cp16(sa + (uint32_t)(r * AP + cc * 8) * 2u,
                 Ab + (size_t)r * GK + cc * 8);
            cp16(sb + (uint32_t)(r * AP + cc * 8) * 2u,
                 Wb + (size_t)r * GK + cc * 8);
        }
        asm volatile("cp.async.commit_group;");
    };

    issue(0, 0);
    issue(1, 1);

    const uint32_t a_lane_off =
        (uint32_t)((wm * 64 + (lane & 15)) * AP + ((lane >> 4) * 8)) * 2u;
    const uint32_t b_lane_off =
        (uint32_t)((wn * 64 + (lane & 7) + ((lane >> 4) & 1) * 8) * AP
                   + (((lane >> 3) & 1) * 8)) * 2u;

    for (int t = 0; t < NT; ++t) {
        if (t + 1 < NT) {
            asm volatile("cp.async.wait_group 1;");
        } else {
            asm volatile("cp.async.wait_group 0;");
        }
        __syncthreads();
        if (t + 2 < NT) issue(t + 2, (t + 2) % 3);

        const uint32_t sa = sbase + (uint32_t)(t % 3) * STGH * 2u;
        const uint32_t aaddr = sa + a_lane_off;
        const uint32_t baddr = sa + ASTGH * 2u + b_lane_off;

#pragma unroll
        for (int ks = 0; ks < 4; ++ks) {
            uint32_t af[4][4], bf[4][4];
#pragma unroll
            for (int ms = 0; ms < 4; ms++)
                ldsm4(af[ms], aaddr + (uint32_t)(ms * 16 * AP + ks * 16) * 2u);
#pragma unroll
            for (int np = 0; np < 4; np++)
                ldsm4(bf[np], baddr + (uint32_t)(np * 16 * AP + ks * 16) * 2u);
#pragma unroll
            for (int ms = 0; ms < 4; ms++)
#pragma unroll
                for (int np = 0; np < 4; np++) {
                    mma_f16(acc[ms][np * 2], af[ms], bf[np]);
                    mma_f16(acc[ms][np * 2 + 1], af[ms], bf[np] + 2);
                }
        }
    }

    float2 bv[8];
#pragma unroll
    for (int ns = 0; ns < 8; ns++) {
        const int col = n0 + wn * 64 + ns * 8 + 2 * (lane & 3);
        bv[ns] = *(const float2*)(bias + col);
    }

    if (half_out) {
        __half* C = (__half*)Cout;
#pragma unroll
        for (int ms = 0; ms < 4; ms++) {
            const int row0 = m0 + wm * 64 + ms * 16 + (lane >> 2);
#pragma unroll
            for (int ns = 0; ns < 8; ns++) {
                const int col = n0 + wn * 64 + ns * 8 + 2 * (lane & 3);
                __half2 v0 = __floats2half2_rn((acc[ms][ns][0] + bv[ns].x) * scale,
                                               (acc[ms][ns][1] + bv[ns].y) * scale);
                __half2 v1 = __floats2half2_rn((acc[ms][ns][2] + bv[ns].x) * scale,
                                               (acc[ms][ns][3] + bv[ns].y) * scale);
                *(__half2*)(C + (size_t)row0 * GN + col) = v0;
                *(__half2*)(C + (size_t)(row0 + 8) * GN + col) = v1;
            }
        }
    } else {
        float* C = (float*)Cout;
#pragma unroll
        for (int ms = 0; ms < 4; ms++) {
            const int row0 = m0 + wm * 64 + ms * 16 + (lane >> 2);
#pragma unroll
            for (int ns = 0; ns < 8; ns++) {
                const int col = n0 + wn * 64 + ns * 8 + 2 * (lane & 3);
                float2 v0 = make_float2(acc[ms][ns][0] + bv[ns].x,
                                        acc[ms][ns][1] + bv[ns].y);
                float2 v1 = make_float2(acc[ms][ns][2] + bv[ns].x,
                                        acc[ms][ns][3] + bv[ns].y);
                *(float2*)(C + (size_t)row0 * GN + col) = v0;
                *(float2*)(C + (size_t)(row0 + 8) * GN + col) = v1;
            }
        }
    }
}

__global__ __launch_bounds__(GEMM_THREADS, 2)
void gemm_qkv(const __half* __restrict__ xq, const __half* __restrict__ xk,
              const __half* __restrict__ xv,
              const __half* __restrict__ wq, const __half* __restrict__ wk,
              const __half* __restrict__ wv,
              const float* __restrict__ bq, const float* __restrict__ bk,
              const float* __restrict__ bv,
              __half* __restrict__ pq, __half* __restrict__ pk,
              __half* __restrict__ pv)
{
    const int z = blockIdx.z;
    const __half* A = (z == 0) ? xq : (z == 1) ? xk : xv;
    const __half* W = (z == 0) ? wq : (z == 1) ? wk : wv;
    const float* bias = (z == 0) ? bq : (z == 1) ? bk : bv;
    __half* C = (z == 0) ? pq : (z == 1) ? pk : pv;
    const float scale = (z == 0) ? (ATT_SCALE * LOG2E) : 1.0f;
    gemm_core(A, W, bias, C, scale, 1, blockIdx.x, blockIdx.y);
}

__global__ __launch_bounds__(GEMM_THREADS, 2)
void gemm_one(const __half* __restrict__ A, const __half* __restrict__ W,
              const float* __restrict__ bias, void* __restrict__ Cout,
              float scale, int half_out)
{
    gemm_core(A, W, bias, Cout, scale, half_out, blockIdx.x, blockIdx.y);
}

// ===========================================================================
// fp16 flash attention v3: per-tile Q fragment reload (frees 32 persistent
// regs), flattened S/PV loops with explicit 2-deep ldsm pipelines.
// ===========================================================================
#define FP 136
#define TILE_H (128 * FP)
#define FLASH_SMEM (TILE_H * 2 * 5)   // 174080 B

__global__ __launch_bounds__(256, 1)
void flash_tc(const __half* __restrict__ Q, const __half* __restrict__ K,
              const __half* __restrict__ V, __half* __restrict__ O)
{
    extern __shared__ __half fsmh[];

    const int qt = (SEQ / 128) - 1 - blockIdx.x;
    const int h = blockIdx.y;
    const int b = blockIdx.z;
    const int q0 = qt * 128;
    const size_t headoff = (size_t)b * SEQ * DMODEL + (size_t)h * HDIM;
    const __half* Qb = Q + headoff;
    const __half* Kb = K + headoff;
    const __half* Vb = V + headoff;

    const int tid = threadIdx.x;
    const int lane = tid & 31;
    const int warp = tid >> 5;
    const int g = lane >> 2;
    const int q4 = lane & 3;

    const uint32_t sQ = smem_u32(fsmh);
    const uint32_t sK0 = sQ + TILE_H * 2u;
    const uint32_t sV0 = sQ + 3u * TILE_H * 2u;

#pragma unroll
    for (int i = 0; i < 8; ++i) {
        const int slot = tid + i * 256;
        const int r = slot >> 4, c = slot & 15;
        cp16(sQ + (uint32_t)(r * FP + c * 8) * 2u,
             Qb + (size_t)(q0 + r) * DMODEL + c * 8);
    }

    auto issue_kv = [&](int kt) {
        const int buf = kt & 1;
        const int k0 = kt * 128;
        const uint32_t dK = sK0 + (uint32_t)buf * TILE_H * 2u;
        const uint32_t dV = sV0 + (uint32_t)buf * TILE_H * 2u;
#pragma unroll
        for (int i = 0; i < 8; ++i) {
            const int slot = tid + i * 256;
            const int r = slot >> 4, c = slot & 15;
            cp16(dK + (uint32_t)(r * FP + c * 8) * 2u,
                 Kb + (size_t)(k0 + r) * DMODEL + c * 8);
            cp16(dV + (uint32_t)(r * FP + c * 8) * 2u,
                 Vb + (size_t)(k0 + r) * DMODEL + c * 8);
        }
        asm volatile("cp.async.commit_group;");
    };

    issue_kv(0);
    if (qt > 0) issue_kv(1);

    float m0 = -INFINITY, m1 = -INFINITY, l0 = 0.0f, l1 = 0.0f;
    float acco[16][4];
#pragma unroll
    for (int j = 0; j < 16; j++)
#pragma unroll
        for (int r = 0; r < 4; r++) acco[j][r] = 0.0f;

    const int ar = warp * 16 + g;

    const uint32_t qa_off =
        (uint32_t)((warp * 16 + (lane & 15)) * FP + ((lane >> 4) * 8)) * 2u;
    const uint32_t kb4_off =
        (uint32_t)(((lane & 7) + ((lane >> 4) & 1) * 8) * FP
                   + (((lane >> 3) & 1) * 8)) * 2u;
    const uint32_t vt4_off =
        (uint32_t)(((lane & 7) + ((lane >> 3) & 1) * 8) * FP
                   + ((lane >> 4) * 8)) * 2u;

    for (int kt = 0; kt <= qt; ++kt) {
        const int buf = kt & 1;
        const uint32_t sKc = sK0 + (uint32_t)buf * TILE_H * 2u;
        const uint32_t sVc = sV0 + (uint32_t)buf * TILE_H * 2u;

        if (kt < qt) {
            asm volatile("cp.async.wait_group 1;");
        } else {
            asm volatile("cp.async.wait_group 0;");
        }
        __syncthreads();

        // Q fragments: reloaded per tile (dies before softmax/PV -> lower
        // peak register pressure than persistent caching)
        uint32_t qf[8][4];
#pragma unroll
        for (int ks = 0; ks < 8; ++ks)
            ldsm4(qf[ks], sQ + qa_off + (uint32_t)(ks * 16) * 2u);

        // ---- S = Q @ K^T : flattened, 2-deep K-fragment pipeline ----
        float accs[16][4];
#pragma unroll
        for (int j = 0; j < 16; j++)
#pragma unroll
            for (int r = 0; r < 4; r++) accs[j][r] = 0.0f;

        {
            uint32_t bb[2][4];
            ldsm4(bb[0], sKc + kb4_off);
#pragma unroll
            for (int i = 0; i < 64; ++i) {
                const int cur = i & 1;
                if (i + 1 < 64) {
                    const int nks = (i + 1) & 7, njp = (i + 1) >> 3;
                    ldsm4(bb[cur ^ 1],
                          sKc + kb4_off + (uint32_t)(njp * 16 * FP + nks * 16) * 2u);
                }
                const int ks = i & 7, jp = i >> 3;
                mma_f16(accs[jp * 2], qf[ks], bb[cur]);
                mma_f16(accs[jp * 2 + 1], qf[ks], bb[cur] + 2);
            }
        }

        if (kt == qt) {
#pragma unroll
            for (int j = 0; j < 16; ++j) {
                const int c0 = j * 8 + 2 * q4;
                if (c0 > ar)          accs[j][0] = -1e30f;
                if (c0 + 1 > ar)      accs[j][1] = -1e30f;
                if (c0 > ar + 8)      accs[j][2] = -1e30f;
                if (c0 + 1 > ar + 8)  accs[j][3] = -1e30f;
            }
        }

        // online softmax in exp2 domain (log2e folded into Q scale)
        float mx0 = -INFINITY, mx1 = -INFINITY;
#pragma unroll
        for (int j = 0; j < 16; ++j) {
            mx0 = fmaxf(mx0, fmaxf(accs[j][0], accs[j][1]));
            mx1 = fmaxf(mx1, fmaxf(accs[j][2], accs[j][3]));
        }
        mx0 = fmaxf(mx0, __shfl_xor_sync(0xffffffffu, mx0, 1));
        mx0 = fmaxf(mx0, __shfl_xor_sync(0xffffffffu, mx0, 2));
        mx1 = fmaxf(mx1, __shfl_xor_sync(0xffffffffu, mx1, 1));
        mx1 = fmaxf(mx1, __shfl_xor_sync(0xffffffffu, mx1, 2));
        const float mn0 = fmaxf(m0, mx0);
        const float mn1 = fmaxf(m1, mx1);
        const float cr0 = exp2f(m0 - mn0);
        const float cr1 = exp2f(m1 - mn1);
        float s0 = 0.0f, s1 = 0.0f;
#pragma unroll
        for (int j = 0; j < 16; ++j) {
            accs[j][0] = exp2f(accs[j][0] - mn0); s0 += accs[j][0];
            accs[j][1] = exp2f(accs[j][1] - mn0); s0 += accs[j][1];
            accs[j][2] = exp2f(accs[j][2] - mn1); s1 += accs[j][2];
            accs[j][3] = exp2f(accs[j][3] - mn1); s1 += accs[j][3];
        }
        s0 += __shfl_xor_sync(0xffffffffu, s0, 1);
        s0 += __shfl_xor_sync(0xffffffffu, s0, 2);
        s1 += __shfl_xor_sync(0xffffffffu, s1, 1);
        s1 += __shfl_xor_sync(0xffffffffu, s1, 2);
        l0 = l0 * cr0 + s0;  m0 = mn0;
        l1 = l1 * cr1 + s1;  m1 = mn1;
#pragma unroll
        for (int j = 0; j < 16; ++j) {
            acco[j][0] *= cr0; acco[j][1] *= cr0;
            acco[j][2] *= cr1; acco[j][3] *= cr1;
        }

        // ---- O += P @ V : flattened, 2-deep V-fragment pipeline ----
        {
            uint32_t bb[2][4];
            uint32_t a[4];
            ldsm4t(bb[0], sVc + vt4_off);
#pragma unroll
            for (int i = 0; i < 64; ++i) {
                const int cur = i & 1;
                if (i + 1 < 64) {
                    const int nt = (i + 1) >> 3, njp = (i + 1) & 7;
                    ldsm4t(bb[cur ^ 1],
                           sVc + vt4_off + (uint32_t)(nt * 16 * FP + njp * 16) * 2u);
                }
                const int t = i >> 3, jp = i & 7;
                if (jp == 0) {
                    a[0] = pack_h2(accs[2 * t][0], accs[2 * t][1]);
                    a[1] = pack_h2(accs[2 * t][2], accs[2 * t][3]);
                    a[2] = pack_h2(accs[2 * t + 1][0], accs[2 * t + 1][1]);
                    a[3] = pack_h2(accs[2 * t + 1][2], accs[2 * t + 1][3]);
                }
                mma_f16(acco[jp * 2], a, bb[cur]);
                mma_f16(acco[jp * 2 + 1], a, bb[cur] + 2);
            }
        }

        __syncthreads();
        if (kt + 2 <= qt) issue_kv(kt + 2);
    }

    const float i0 = 1.0f / l0;
    const float i1 = 1.0f / l1;
#pragma unroll
    for (int j = 0; j < 16; ++j) {
        *(__half2*)(O + headoff + (size_t)(q0 + ar) * DMODEL + j * 8 + 2 * q4) =
            __floats2half2_rn(acco[j][0] * i0, acco[j][1] * i0);
        *(__half2*)(O + headoff + (size_t)(q0 + ar + 8) * DMODEL + j * 8 + 2 * q4) =
            __floats2half2_rn(acco[j][2] * i1, acco[j][3] * i1);
    }
}

// ---------------------------------------------------------------------------
extern "C" void kernel_launch(void* const* d_in, const int* in_sizes, int n_in,
                              void* d_out, int out_size)
{
    const float* query = (const float*)d_in[0];
    const float* key_i = (const float*)d_in[1];
    const float* value = (const float*)d_in[2];
    const float* Wq = (const float*)d_in[3];
    const float* bq = (const float*)d_in[4];
    const float* Wk = (const float*)d_in[5];
    const float* bk = (const float*)d_in[6];
    const float* Wv = (const float*)d_in[7];
    const float* bv = (const float*)d_in[8];
    const float* Wo = (const float*)d_in[9];
    const float* bo = (const float*)d_in[10];
    float* out = (float*)d_out;

    __half *xq, *xk, *xv, *wq, *wk, *wv, *wo, *pq, *pk, *pv, *pa;
    cudaGetSymbolAddress((void**)&xq, hx_q);
    cudaGetSymbolAddress((void**)&xk, hx_k);
    cudaGetSymbolAddress((void**)&xv, hx_v);
    cudaGetSymbolAddress((void**)&wq, hw_q);
    cudaGetSymbolAddress((void**)&wk, hw_k);
    cudaGetSymbolAddress((void**)&wv, hw_v);
    cudaGetSymbolAddress((void**)&wo, hw_o);
    cudaGetSymbolAddress((void**)&pq, h_q);
    cudaGetSymbolAddress((void**)&pk, h_k);
    cudaGetSymbolAddress((void**)&pv, h_v);
    cudaGetSymbolAddress((void**)&pa, h_a);

    const int act4 = (MROWS * DMODEL) / 4;
    const int w4 = (DMODEL * DMODEL) / 4;
    conv_act<<<dim3((act4 + 255) / 256, 3), 256>>>(
        (const float4*)query, (const float4*)key_i, (const float4*)value,
        (uint2*)xq, (uint2*)xk, (uint2*)xv, act4);
    conv_w<<<dim3((w4 + 255) / 256, 4), 256>>>(
        (const float4*)Wq, (const float4*)Wk, (const float4*)Wv,
        (const float4*)Wo, (uint2*)wq, (uint2*)wk, (uint2*)wv, (uint2*)wo, w4);

    cudaFuncSetAttribute(gemm_qkv, cudaFuncAttributeMaxDynamicSharedMemorySize,
                         GEMM_SMEM);
    cudaFuncSetAttribute(gemm_one, cudaFuncAttributeMaxDynamicSharedMemorySize,
                         GEMM_SMEM);

    gemm_qkv<<<dim3(GN / TBN, MROWS / TBM, 3), GEMM_THREADS, GEMM_SMEM>>>(
        xq, xk, xv, wq, wk, wv, bq, bk, bv, pq, pk, pv);

    cudaFuncSetAttribute(flash_tc, cudaFuncAttributeMaxDynamicSharedMemorySize,
                         FLASH_SMEM);
    const dim3 agrid(SEQ / 128, NHEAD, BATCH);
    flash_tc<<<agrid, 256, FLASH_SMEM>>>(pq, pk, pv, pa);

    gemm_one<<<dim3(GN / TBN, MROWS / TBM), GEMM_THREADS, GEMM_SMEM>>>(
        pa, wo, bo, out, 1.0f, 0);
}

// round 11
// speedup vs baseline: 2.5111x; 1.0082x over previous
#include <cuda_runtime.h>
#include <cuda_fp16.h>
#include <math.h>
#include <stdint.h>

#define BATCH 2
#define SEQ 2048
#define DMODEL 2048
#define NHEAD 16
#define HDIM 128
#define MROWS (BATCH * SEQ)          // 4096
#define ATT_SCALE 0.08838834764831845f  // 1/sqrt(128)
#define LOG2E 1.4426950408889634f

// Scratch (device globals: allocation-free per harness rules)
__device__ __half hx_q[(size_t)MROWS * DMODEL];   // fp16 inputs
__device__ __half hx_k[(size_t)MROWS * DMODEL];
__device__ __half hx_v[(size_t)MROWS * DMODEL];
__device__ __half hw_q[(size_t)DMODEL * DMODEL];  // fp16 weights
__device__ __half hw_k[(size_t)DMODEL * DMODEL];
__device__ __half hw_v[(size_t)DMODEL * DMODEL];
__device__ __half hw_o[(size_t)DMODEL * DMODEL];
__device__ __half h_q[(size_t)MROWS * DMODEL];    // projected q (pre-scaled)
__device__ __half h_k[(size_t)MROWS * DMODEL];
__device__ __half h_v[(size_t)MROWS * DMODEL];
__device__ __half h_a[(size_t)MROWS * DMODEL];    // attention output

// ===========================================================================
// helpers
// ===========================================================================
__device__ __forceinline__ uint32_t smem_u32(const void* p) {
    uint32_t a;
    asm("{ .reg .u64 t; cvta.to.shared.u64 t, %1; cvt.u32.u64 %0, t; }"
        : "=r"(a) : "l"(p));
    return a;
}

__device__ __forceinline__ void cp16(uint32_t dst, const void* src) {
    asm volatile("cp.async.cg.shared.global [%0], [%1], 16;"
                 :: "r"(dst), "l"(src));
}

__device__ __forceinline__ void mma_f16(float* d, const uint32_t* a,
                                        const uint32_t* b)
{
    asm volatile(
        "mma.sync.aligned.m16n8k16.row.col.f32.f16.f16.f32 "
        "{%0,%1,%2,%3}, {%4,%5,%6,%7}, {%8,%9}, {%0,%1,%2,%3};"
        : "+f"(d[0]), "+f"(d[1]), "+f"(d[2]), "+f"(d[3])
        : "r"(a[0]), "r"(a[1]), "r"(a[2]), "r"(a[3]),
          "r"(b[0]), "r"(b[1]));
}

__device__ __forceinline__ void ldsm4(uint32_t* r, uint32_t a) {
    asm volatile("ldmatrix.sync.aligned.m8n8.x4.shared.b16 {%0,%1,%2,%3}, [%4];"
                 : "=r"(r[0]), "=r"(r[1]), "=r"(r[2]), "=r"(r[3]) : "r"(a));
}
__device__ __forceinline__ void ldsm4t(uint32_t* r, uint32_t a) {
    asm volatile("ldmatrix.sync.aligned.m8n8.x4.trans.shared.b16 {%0,%1,%2,%3}, [%4];"
                 : "=r"(r[0]), "=r"(r[1]), "=r"(r[2]), "=r"(r[3]) : "r"(a));
}

__device__ __forceinline__ uint32_t pack_h2(float x, float y) {
    __half2 h = __floats2half2_rn(x, y);
    return *(uint32_t*)&h;
}

// ===========================================================================
// merged fp32 -> fp16 conversion passes
// ===========================================================================
__device__ __forceinline__ uint2 cvt4(float4 v) {
    union { __half2 h[2]; uint2 u; } p;
    p.h[0] = __floats2half2_rn(v.x, v.y);
    p.h[1] = __floats2half2_rn(v.z, v.w);
    return p.u;
}

__global__ void conv_act(const float4* __restrict__ q,
                         const float4* __restrict__ k,
                         const float4* __restrict__ v,
                         uint2* __restrict__ oq, uint2* __restrict__ ok,
                         uint2* __restrict__ ov, int n4)
{
    int i = blockIdx.x * blockDim.x + threadIdx.x;
    if (i >= n4) return;
    const float4* src = (blockIdx.y == 0) ? q : (blockIdx.y == 1) ? k : v;
    uint2* dst = (blockIdx.y == 0) ? oq : (blockIdx.y == 1) ? ok : ov;
    dst[i] = cvt4(src[i]);
}

__global__ void conv_w(const float4* __restrict__ w0,
                       const float4* __restrict__ w1,
                       const float4* __restrict__ w2,
                       const float4* __restrict__ w3,
                       uint2* __restrict__ o0, uint2* __restrict__ o1,
                       uint2* __restrict__ o2, uint2* __restrict__ o3, int n4)
{
    int i = blockIdx.x * blockDim.x + threadIdx.x;
    if (i >= n4) return;
    const float4* src = (blockIdx.y == 0) ? w0 : (blockIdx.y == 1) ? w1
                      : (blockIdx.y == 2) ? w2 : w3;
    uint2* dst = (blockIdx.y == 0) ? o0 : (blockIdx.y == 1) ? o1
               : (blockIdx.y == 2) ? o2 : o3;
    dst[i] = cvt4(src[i]);
}

// ===========================================================================
// fp16 mma.sync GEMM core (unchanged from R9 win): CTA 128x128, 128 threads,
// 4 warps (2x2 of 64x64), BK=64, 3-stage cp.async, 2 CTAs/SM.
// ===========================================================================
#define TBM 128
#define TBN 128
#define GK 2048
#define GN 2048
#define GBKH 64
#define AP 72
#define ASTGH (TBM * AP)
#define BSTGH (TBN * AP)
#define STGH (ASTGH + BSTGH)
#define GEMM_SMEM (3 * STGH * 2)      // 110592 B
#define NT (GK / GBKH)                // 32
#define GEMM_THREADS 128

__device__ __forceinline__ void gemm_core(
    const __half* __restrict__ A, const __half* __restrict__ W,
    const float* __restrict__ bias, void* __restrict__ Cout,
    float scale, int half_out, int bx, int by)
{
    extern __shared__ __half gsmh[];

    const int tid = threadIdx.x;
    const int lane = tid & 31;
    const int warp = tid >> 5;
    const int wm = warp & 1;
    const int wn = warp >> 1;
    const int m0 = by * TBM;
    const int n0 = bx * TBN;

    const uint32_t sbase = smem_u32(gsmh);
    const int cr = tid >> 3;
    const int cc = tid & 7;

    float acc[4][8][4];
#pragma unroll
    for (int i = 0; i < 4; i++)
#pragma unroll
        for (int j = 0; j < 8; j++)
#pragma unroll
            for (int r = 0; r < 4; r++) acc[i][j][r] = 0.0f;

    auto issue = [&](int t, int buf) {
        const __half* Ab = A + (size_t)m0 * GK + t * GBKH;
        const __half* Wb = W + (size_t)n0 * GK + t * GBKH;
        const uint32_t sa = sbase + (uint32_t)buf * STGH * 2u;
        const uint32_t sb = sa + ASTGH * 2u;
#pragma unroll
        for (int i = 0; i < 8; i++) {
            const int r = cr + i * 16;
            cp16(sa + (uint32_t)(r * AP + cc * 8) * 2u,
                 Ab + (size_t)r * GK + cc * 8);
            cp16(sb + (uint32_t)(r * AP + cc * 8) * 2u,
                 Wb + (size_t)r * GK + cc * 8);
        }
        asm volatile("cp.async.commit_group;");
    };

    issue(0, 0);
    issue(1, 1);

    const uint32_t a_lane_off =
        (uint32_t)((wm * 64 + (lane & 15)) * AP + ((lane >> 4) * 8)) * 2u;
    const uint32_t b_lane_off =
        (uint32_t)((wn * 64 + (lane & 7) + ((lane >> 4) & 1) * 8) * AP
                   + (((lane >> 3) & 1) * 8)) * 2u;

    for (int t = 0; t < NT; ++t) {
        if (t + 1 < NT) {
            asm volatile("cp.async.wait_group 1;");
        } else {
            asm volatile("cp.async.wait_group 0;");
        }
        __syncthreads();
        if (t + 2 < NT) issue(t + 2, (t + 2) % 3);

        const uint32_t sa = sbase + (uint32_t)(t % 3) * STGH * 2u;
        const uint32_t aaddr = sa + a_lane_off;
        const uint32_t baddr = sa + ASTGH * 2u + b_lane_off;

#pragma unroll
        for (int ks = 0; ks < 4; ++ks) {
            uint32_t af[4][4], bf[4][4];
#pragma unroll
            for (int ms = 0; ms < 4; ms++)
                ldsm4(af[ms], aaddr + (uint32_t)(ms * 16 * AP + ks * 16) * 2u);
#pragma unroll
            for (int np = 0; np < 4; np++)
                ldsm4(bf[np], baddr + (uint32_t)(np * 16 * AP + ks * 16) * 2u);
#pragma unroll
            for (int ms = 0; ms < 4; ms++)
#pragma unroll
                for (int np = 0; np < 4; np++) {
                    mma_f16(acc[ms][np * 2], af[ms], bf[np]);
                    mma_f16(acc[ms][np * 2 + 1], af[ms], bf[np] + 2);
                }
        }
    }

    float2 bv[8];
#pragma unroll
    for (int ns = 0; ns < 8; ns++) {
        const int col = n0 + wn * 64 + ns * 8 + 2 * (lane & 3);
        bv[ns] = *(const float2*)(bias + col);
    }

    if (half_out) {
        __half* C = (__half*)Cout;
#pragma unroll
        for (int ms = 0; ms < 4; ms++) {
            const int row0 = m0 + wm * 64 + ms * 16 + (lane >> 2);
#pragma unroll
            for (int ns = 0; ns < 8; ns++) {
                const int col = n0 + wn * 64 + ns * 8 + 2 * (lane & 3);
                __half2 v0 = __floats2half2_rn((acc[ms][ns][0] + bv[ns].x) * scale,
                                               (acc[ms][ns][1] + bv[ns].y) * scale);
                __half2 v1 = __floats2half2_rn((acc[ms][ns][2] + bv[ns].x) * scale,
                                               (acc[ms][ns][3] + bv[ns].y) * scale);
                *(__half2*)(C + (size_t)row0 * GN + col) = v0;
                *(__half2*)(C + (size_t)(row0 + 8) * GN + col) = v1;
            }
        }
    } else {
        float* C = (float*)Cout;
#pragma unroll
        for (int ms = 0; ms < 4; ms++) {
            const int row0 = m0 + wm * 64 + ms * 16 + (lane >> 2);
#pragma unroll
            for (int ns = 0; ns < 8; ns++) {
                const int col = n0 + wn * 64 + ns * 8 + 2 * (lane & 3);
                float2 v0 = make_float2(acc[ms][ns][0] + bv[ns].x,
                                        acc[ms][ns][1] + bv[ns].y);
                float2 v1 = make_float2(acc[ms][ns][2] + bv[ns].x,
                                        acc[ms][ns][3] + bv[ns].y);
                *(float2*)(C + (size_t)row0 * GN + col) = v0;
                *(float2*)(C + (size_t)(row0 + 8) * GN + col) = v1;
            }
        }
    }
}

__global__ __launch_bounds__(GEMM_THREADS, 2)
void gemm_qkv(const __half* __restrict__ xq, const __half* __restrict__ xk,
              const __half* __restrict__ xv,
              const __half* __restrict__ wq, const __half* __restrict__ wk,
              const __half* __restrict__ wv,
              const float* __restrict__ bq, const float* __restrict__ bk,
              const float* __restrict__ bv,
              __half* __restrict__ pq, __half* __restrict__ pk,
              __half* __restrict__ pv)
{
    const int z = blockIdx.z;
    const __half* A = (z == 0) ? xq : (z == 1) ? xk : xv;
    const __half* W = (z == 0) ? wq : (z == 1) ? wk : wv;
    const float* bias = (z == 0) ? bq : (z == 1) ? bk : bv;
    __half* C = (z == 0) ? pq : (z == 1) ? pk : pv;
    const float scale = (z == 0) ? (ATT_SCALE * LOG2E) : 1.0f;
    gemm_core(A, W, bias, C, scale, 1, blockIdx.x, blockIdx.y);
}

__global__ __launch_bounds__(GEMM_THREADS, 2)
void gemm_one(const __half* __restrict__ A, const __half* __restrict__ W,
              const float* __restrict__ bias, void* __restrict__ Cout,
              float scale, int half_out)
{
    gemm_core(A, W, bias, Cout, scale, half_out, blockIdx.x, blockIdx.y);
}

// ===========================================================================
// fp16 flash attention v4: 64-q-row CTAs, 128 threads, KV tile 64,
// 2 CTAs/SM (87KB smem each) -> two independent streams per SM.
// ===========================================================================
#define FQ 64                          // q rows per CTA
#define FK 64                          // kv rows per tile
#define FP 136
#define QTILE_H (FQ * FP)              // halves
#define KTILE_H (FK * FP)
#define FLASH_SMEM ((QTILE_H + 4 * KTILE_H) * 2)   // 87040 B
#define FLASH_THREADS 128
#define NQT (SEQ / FQ)                 // 32

__global__ __launch_bounds__(FLASH_THREADS, 2)
void flash_tc(const __half* __restrict__ Q, const __half* __restrict__ K,
              const __half* __restrict__ V, __half* __restrict__ O)
{
    extern __shared__ __half fsmh[];

    const int qt = NQT - 1 - blockIdx.x;   // heavy tiles first
    const int h = blockIdx.y;
    const int b = blockIdx.z;
    const int q0 = qt * FQ;
    const size_t headoff = (size_t)b * SEQ * DMODEL + (size_t)h * HDIM;
    const __half* Qb = Q + headoff;
    const __half* Kb = K + headoff;
    const __half* Vb = V + headoff;

    const int tid = threadIdx.x;
    const int lane = tid & 31;
    const int warp = tid >> 5;       // 0..3, owns q rows [warp*16, warp*16+16)
    const int g = lane >> 2;
    const int q4 = lane & 3;

    const uint32_t sQ = smem_u32(fsmh);
    const uint32_t sK0 = sQ + QTILE_H * 2u;              // 2 K buffers
    const uint32_t sV0 = sQ + (QTILE_H + 2 * KTILE_H) * 2u;  // 2 V buffers

    // Q tile: 64 rows x 16 chunks = 1024 slots, 8 per thread
#pragma unroll
    for (int i = 0; i < 8; ++i) {
        const int slot = tid + i * FLASH_THREADS;
        const int r = slot >> 4, c = slot & 15;
        cp16(sQ + (uint32_t)(r * FP + c * 8) * 2u,
             Qb + (size_t)(q0 + r) * DMODEL + c * 8);
    }

    auto issue_kv = [&](int kt) {
        const int buf = kt & 1;
        const int k0 = kt * FK;
        const uint32_t dK = sK0 + (uint32_t)buf * KTILE_H * 2u;
        const uint32_t dV = sV0 + (uint32_t)buf * KTILE_H * 2u;
#pragma unroll
        for (int i = 0; i < 8; ++i) {
            const int slot = tid + i * FLASH_THREADS;
            const int r = slot >> 4, c = slot & 15;
            cp16(dK + (uint32_t)(r * FP + c * 8) * 2u,
                 Kb + (size_t)(k0 + r) * DMODEL + c * 8);
            cp16(dV + (uint32_t)(r * FP + c * 8) * 2u,
                 Vb + (size_t)(k0 + r) * DMODEL + c * 8);
        }
        asm volatile("cp.async.commit_group;");
    };

    issue_kv(0);
    if (qt > 0) issue_kv(1);

    float m0 = -INFINITY, m1 = -INFINITY, l0 = 0.0f, l1 = 0.0f;
    float acco[16][4];
#pragma unroll
    for (int j = 0; j < 16; j++)
#pragma unroll
        for (int r = 0; r < 4; r++) acco[j][r] = 0.0f;

    const int ar = warp * 16 + g;

    const uint32_t qa_off =
        (uint32_t)((warp * 16 + (lane & 15)) * FP + ((lane >> 4) * 8)) * 2u;
    const uint32_t kb4_off =
        (uint32_t)(((lane & 7) + ((lane >> 4) & 1) * 8) * FP
                   + (((lane >> 3) & 1) * 8)) * 2u;
    const uint32_t vt4_off =
        (uint32_t)(((lane & 7) + ((lane >> 3) & 1) * 8) * FP
                   + ((lane >> 4) * 8)) * 2u;

    uint32_t qf[8][4];
    bool qloaded = false;

    for (int kt = 0; kt <= qt; ++kt) {
        const int buf = kt & 1;
        const uint32_t sKc = sK0 + (uint32_t)buf * KTILE_H * 2u;
        const uint32_t sVc = sV0 + (uint32_t)buf * KTILE_H * 2u;

        if (kt < qt) {
            asm volatile("cp.async.wait_group 1;");
        } else {
            asm volatile("cp.async.wait_group 0;");
        }
        __syncthreads();

        if (!qloaded) {
#pragma unroll
            for (int ks = 0; ks < 8; ++ks)
                ldsm4(qf[ks], sQ + qa_off + (uint32_t)(ks * 16) * 2u);
            qloaded = true;
        }

        // ---- S = Q @ K^T : 16 q x 64 kv per warp (32 MMAs) ----
        float accs[8][4];
#pragma unroll
        for (int j = 0; j < 8; j++)
#pragma unroll
            for (int r = 0; r < 4; r++) accs[j][r] = 0.0f;

#pragma unroll
        for (int jp = 0; jp < 4; ++jp) {
#pragma unroll
            for (int ks = 0; ks < 8; ++ks) {
                uint32_t bb[4];
                ldsm4(bb, sKc + kb4_off + (uint32_t)(jp * 16 * FP + ks * 16) * 2u);
                mma_f16(accs[jp * 2], qf[ks], bb);
                mma_f16(accs[jp * 2 + 1], qf[ks], bb + 2);
            }
        }

        if (kt == qt) {
#pragma unroll
            for (int j = 0; j < 8; ++j) {
                const int c0 = j * 8 + 2 * q4;
                if (c0 > ar)          accs[j][0] = -1e30f;
                if (c0 + 1 > ar)      accs[j][1] = -1e30f;
                if (c0 > ar + 8)      accs[j][2] = -1e30f;
                if (c0 + 1 > ar + 8)  accs[j][3] = -1e30f;
            }
        }

        // online softmax in exp2 domain (log2e folded into Q scale)
        float mx0 = -INFINITY, mx1 = -INFINITY;
#pragma unroll
        for (int j = 0; j < 8; ++j) {
            mx0 = fmaxf(mx0, fmaxf(accs[j][0], accs[j][1]));
            mx1 = fmaxf(mx1, fmaxf(accs[j][2], accs[j][3]));
        }
        mx0 = fmaxf(mx0, __shfl_xor_sync(0xffffffffu, mx0, 1));
        mx0 = fmaxf(mx0, __shfl_xor_sync(0xffffffffu, mx0, 2));
        mx1 = fmaxf(mx1, __shfl_xor_sync(0xffffffffu, mx1, 1));
        mx1 = fmaxf(mx1, __shfl_xor_sync(0xffffffffu, mx1, 2));
        const float mn0 = fmaxf(m0, mx0);
        const float mn1 = fmaxf(m1, mx1);
        const float cr0 = exp2f(m0 - mn0);
        const float cr1 = exp2f(m1 - mn1);
        float s0 = 0.0f, s1 = 0.0f;
#pragma unroll
        for (int j = 0; j < 8; ++j) {
            accs[j][0] = exp2f(accs[j][0] - mn0); s0 += accs[j][0];
            accs[j][1] = exp2f(accs[j][1] - mn0); s0 += accs[j][1];
            accs[j][2] = exp2f(accs[j][2] - mn1); s1 += accs[j][2];
            accs[j][3] = exp2f(accs[j][3] - mn1); s1 += accs[j][3];
        }
        s0 += __shfl_xor_sync(0xffffffffu, s0, 1);
        s0 += __shfl_xor_sync(0xffffffffu, s0, 2);
        s1 += __shfl_xor_sync(0xffffffffu, s1, 1);
        s1 += __shfl_xor_sync(0xffffffffu, s1, 2);
        l0 = l0 * cr0 + s0;  m0 = mn0;
        l1 = l1 * cr1 + s1;  m1 = mn1;
#pragma unroll
        for (int j = 0; j < 16; ++j) {
            acco[j][0] *= cr0; acco[j][1] *= cr0;
            acco[j][2] *= cr1; acco[j][3] *= cr1;
        }

        // ---- O += P @ V : P in registers; 4 k16 steps x 8 HDIM blocks ----
#pragma unroll
        for (int t = 0; t < 4; ++t) {
            uint32_t a[4];
            a[0] = pack_h2(accs[2 * t][0], accs[2 * t][1]);
            a[1] = pack_h2(accs[2 * t][2], accs[2 * t][3]);
            a[2] = pack_h2(accs[2 * t + 1][0], accs[2 * t + 1][1]);
            a[3] = pack_h2(accs[2 * t + 1][2], accs[2 * t + 1][3]);
#pragma unroll
            for (int jp = 0; jp < 8; ++jp) {
                uint32_t bb[4];
                ldsm4t(bb, sVc + vt4_off + (uint32_t)(t * 16 * FP + jp * 16) * 2u);
                mma_f16(acco[jp * 2], a, bb);
                mma_f16(acco[jp * 2 + 1], a, bb + 2);
            }
        }

        __syncthreads();
        if (kt + 2 <= qt) issue_kv(kt + 2);
    }

    const float i0 = 1.0f / l0;
    const float i1 = 1.0f / l1;
#pragma unroll
    for (int j = 0; j < 16; ++j) {
        *(__half2*)(O + headoff + (size_t)(q0 + ar) * DMODEL + j * 8 + 2 * q4) =
            __floats2half2_rn(acco[j][0] * i0, acco[j][1] * i0);
        *(__half2*)(O + headoff + (size_t)(q0 + ar + 8) * DMODEL + j * 8 + 2 * q4) =
            __floats2half2_rn(acco[j][2] * i1, acco[j][3] * i1);
    }
}

// ---------------------------------------------------------------------------
extern "C" void kernel_launch(void* const* d_in, const int* in_sizes, int n_in,
                              void* d_out, int out_size)
{
    const float* query = (const float*)d_in[0];
    const float* key_i = (const float*)d_in[1];
    const float* value = (const float*)d_in[2];
    const float* Wq = (const float*)d_in[3];
    const float* bq = (const float*)d_in[4];
    const float* Wk = (const float*)d_in[5];
    const float* bk = (const float*)d_in[6];
    const float* Wv = (const float*)d_in[7];
    const float* bv = (const float*)d_in[8];
    const float* Wo = (const float*)d_in[9];
    const float* bo = (const float*)d_in[10];
    float* out = (float*)d_out;

    __half *xq, *xk, *xv, *wq, *wk, *wv, *wo, *pq, *pk, *pv, *pa;
    cudaGetSymbolAddress((void**)&xq, hx_q);
    cudaGetSymbolAddress((void**)&xk, hx_k);
    cudaGetSymbolAddress((void**)&xv, hx_v);
    cudaGetSymbolAddress((void**)&wq, hw_q);
    cudaGetSymbolAddress((void**)&wk, hw_k);
    cudaGetSymbolAddress((void**)&wv, hw_v);
    cudaGetSymbolAddress((void**)&wo, hw_o);
    cudaGetSymbolAddress((void**)&pq, h_q);
    cudaGetSymbolAddress((void**)&pk, h_k);
    cudaGetSymbolAddress((void**)&pv, h_v);
    cudaGetSymbolAddress((void**)&pa, h_a);

    const int act4 = (MROWS * DMODEL) / 4;
    const int w4 = (DMODEL * DMODEL) / 4;
    conv_act<<<dim3((act4 + 255) / 256, 3), 256>>>(
        (const float4*)query, (const float4*)key_i, (const float4*)value,
        (uint2*)xq, (uint2*)xk, (uint2*)xv, act4);
    conv_w<<<dim3((w4 + 255) / 256, 4), 256>>>(
        (const float4*)Wq, (const float4*)Wk, (const float4*)Wv,
        (const float4*)Wo, (uint2*)wq, (uint2*)wk, (uint2*)wv, (uint2*)wo, w4);

    cudaFuncSetAttribute(gemm_qkv, cudaFuncAttributeMaxDynamicSharedMemorySize,
                         GEMM_SMEM);
    cudaFuncSetAttribute(gemm_one, cudaFuncAttributeMaxDynamicSharedMemorySize,
                         GEMM_SMEM);

    gemm_qkv<<<dim3(GN / TBN, MROWS / TBM, 3), GEMM_THREADS, GEMM_SMEM>>>(
        xq, xk, xv, wq, wk, wv, bq, bk, bv, pq, pk, pv);

    cudaFuncSetAttribute(flash_tc, cudaFuncAttributeMaxDynamicSharedMemorySize,
                         FLASH_SMEM);
    const dim3 agrid(NQT, NHEAD, BATCH);   // 1024 CTAs
    flash_tc<<<agrid, FLASH_THREADS, FLASH_SMEM>>>(pq, pk, pv, pa);

    gemm_one<<<dim3(GN / TBN, MROWS / TBM), GEMM_THREADS, GEMM_SMEM>>>(
        pa, wo, bo, out, 1.0f, 0);
}

// round 12
// speedup vs baseline: 2.5446x; 1.0134x over previous
#include <cuda_runtime.h>
#include <cuda_fp16.h>
#include <math.h>
#include <stdint.h>

#define BATCH 2
#define SEQ 2048
#define DMODEL 2048
#define NHEAD 16
#define HDIM 128
#define MROWS (BATCH * SEQ)          // 4096
#define ATT_SCALE 0.08838834764831845f  // 1/sqrt(128)
#define LOG2E 1.4426950408889634f

// Scratch (device globals: allocation-free per harness rules)
__device__ __half hx_q[(size_t)MROWS * DMODEL];   // fp16 inputs
__device__ __half hx_k[(size_t)MROWS * DMODEL];
__device__ __half hx_v[(size_t)MROWS * DMODEL];
__device__ __half hw_q[(size_t)DMODEL * DMODEL];  // fp16 weights
__device__ __half hw_k[(size_t)DMODEL * DMODEL];
__device__ __half hw_v[(size_t)DMODEL * DMODEL];
__device__ __half hw_o[(size_t)DMODEL * DMODEL];
__device__ __half h_q[(size_t)MROWS * DMODEL];    // projected q (pre-scaled)
__device__ __half h_k[(size_t)MROWS * DMODEL];
__device__ __half h_v[(size_t)MROWS * DMODEL];
__device__ __half h_a[(size_t)MROWS * DMODEL];    // attention output

// ===========================================================================
// helpers
// ===========================================================================
__device__ __forceinline__ uint32_t smem_u32(const void* p) {
    uint32_t a;
    asm("{ .reg .u64 t; cvta.to.shared.u64 t, %1; cvt.u32.u64 %0, t; }"
        : "=r"(a) : "l"(p));
    return a;
}

__device__ __forceinline__ void cp16(uint32_t dst, const void* src) {
    asm volatile("cp.async.cg.shared.global [%0], [%1], 16;"
                 :: "r"(dst), "l"(src));
}

__device__ __forceinline__ void mma_f16(float* d, const uint32_t* a,
                                        const uint32_t* b)
{
    asm volatile(
        "mma.sync.aligned.m16n8k16.row.col.f32.f16.f16.f32 "
        "{%0,%1,%2,%3}, {%4,%5,%6,%7}, {%8,%9}, {%0,%1,%2,%3};"
        : "+f"(d[0]), "+f"(d[1]), "+f"(d[2]), "+f"(d[3])
        : "r"(a[0]), "r"(a[1]), "r"(a[2]), "r"(a[3]),
          "r"(b[0]), "r"(b[1]));
}

__device__ __forceinline__ void ldsm4(uint32_t* r, uint32_t a) {
    asm volatile("ldmatrix.sync.aligned.m8n8.x4.shared.b16 {%0,%1,%2,%3}, [%4];"
                 : "=r"(r[0]), "=r"(r[1]), "=r"(r[2]), "=r"(r[3]) : "r"(a));
}
__device__ __forceinline__ void ldsm4t(uint32_t* r, uint32_t a) {
    asm volatile("ldmatrix.sync.aligned.m8n8.x4.trans.shared.b16 {%0,%1,%2,%3}, [%4];"
                 : "=r"(r[0]), "=r"(r[1]), "=r"(r[2]), "=r"(r[3]) : "r"(a));
}

// exp2 on a packed pair of (fp32 -> fp16) values; result is an MMA A-frag word
__device__ __forceinline__ uint32_t ex2_h2(float x, float y) {
    __half2 hv = __floats2half2_rn(x, y);
    uint32_t u = *(uint32_t*)&hv;
    uint32_t r;
    asm("ex2.approx.f16x2 %0, %1;" : "=r"(r) : "r"(u));
    return r;
}

// ===========================================================================
// merged fp32 -> fp16 conversion passes (4 float4 per thread for MLP)
// ===========================================================================
__device__ __forceinline__ uint2 cvt4(float4 v) {
    union { __half2 h[2]; uint2 u; } p;
    p.h[0] = __floats2half2_rn(v.x, v.y);
    p.h[1] = __floats2half2_rn(v.z, v.w);
    return p.u;
}

__global__ void conv_act(const float4* __restrict__ q,
                         const float4* __restrict__ k,
                         const float4* __restrict__ v,
                         uint2* __restrict__ oq, uint2* __restrict__ ok,
                         uint2* __restrict__ ov, int n4)
{
    const float4* src = (blockIdx.y == 0) ? q : (blockIdx.y == 1) ? k : v;
    uint2* dst = (blockIdx.y == 0) ? oq : (blockIdx.y == 1) ? ok : ov;
    const int base = blockIdx.x * 1024 + threadIdx.x;
    float4 v0 = src[base];
    float4 v1 = src[base + 256];
    float4 v2 = src[base + 512];
    float4 v3 = src[base + 768];
    dst[base] = cvt4(v0);
    dst[base + 256] = cvt4(v1);
    dst[base + 512] = cvt4(v2);
    dst[base + 768] = cvt4(v3);
}

__global__ void conv_w(const float4* __restrict__ w0,
                       const float4* __restrict__ w1,
                       const float4* __restrict__ w2,
                       const float4* __restrict__ w3,
                       uint2* __restrict__ o0, uint2* __restrict__ o1,
                       uint2* __restrict__ o2, uint2* __restrict__ o3, int n4)
{
    const float4* src = (blockIdx.y == 0) ? w0 : (blockIdx.y == 1) ? w1
                      : (blockIdx.y == 2) ? w2 : w3;
    uint2* dst = (blockIdx.y == 0) ? o0 : (blockIdx.y == 1) ? o1
               : (blockIdx.y == 2) ? o2 : o3;
    const int base = blockIdx.x * 1024 + threadIdx.x;
    float4 v0 = src[base];
    float4 v1 = src[base + 256];
    float4 v2 = src[base + 512];
    float4 v3 = src[base + 768];
    dst[base] = cvt4(v0);
    dst[base + 256] = cvt4(v1);
    dst[base + 512] = cvt4(v2);
    dst[base + 768] = cvt4(v3);
}

// ===========================================================================
// fp16 mma.sync GEMM core (unchanged from R9 win): CTA 128x128, 128 threads,
// 4 warps (2x2 of 64x64), BK=64, 3-stage cp.async, 2 CTAs/SM.
// ===========================================================================
#define TBM 128
#define TBN 128
#define GK 2048
#define GN 2048
#define GBKH 64
#define AP 72
#define ASTGH (TBM * AP)
#define BSTGH (TBN * AP)
#define STGH (ASTGH + BSTGH)
#define GEMM_SMEM (3 * STGH * 2)      // 110592 B
#define NT (GK / GBKH)                // 32
#define GEMM_THREADS 128

__device__ __forceinline__ void gemm_core(
    const __half* __restrict__ A, const __half* __restrict__ W,
    const float* __restrict__ bias, void* __restrict__ Cout,
    float scale, int half_out, int bx, int by)
{
    extern __shared__ __half gsmh[];

    const int tid = threadIdx.x;
    const int lane = tid & 31;
    const int warp = tid >> 5;
    const int wm = warp & 1;
    const int wn = warp >> 1;
    const int m0 = by * TBM;
    const int n0 = bx * TBN;

    const uint32_t sbase = smem_u32(gsmh);
    const int cr = tid >> 3;
    const int cc = tid & 7;

    float acc[4][8][4];
#pragma unroll
    for (int i = 0; i < 4; i++)
#pragma unroll
        for (int j = 0; j < 8; j++)
#pragma unroll
            for (int r = 0; r < 4; r++) acc[i][j][r] = 0.0f;

    auto issue = [&](int t, int buf) {
        const __half* Ab = A + (size_t)m0 * GK + t * GBKH;
        const __half* Wb = W + (size_t)n0 * GK + t * GBKH;
        const uint32_t sa = sbase + (uint32_t)buf * STGH * 2u;
        const uint32_t sb = sa + ASTGH * 2u;
#pragma unroll
        for (int i = 0; i < 8; i++) {
            const int r = cr + i * 16;
            cp16(sa + (uint32_t)(r * AP + cc * 8) * 2u,
                 Ab + (size_t)r * GK + cc * 8);
            cp16(sb + (uint32_t)(r * AP + cc * 8) * 2u,
                 Wb + (size_t)r * GK + cc * 8);
        }
        asm volatile("cp.async.commit_group;");
    };

    issue(0, 0);
    issue(1, 1);

    const uint32_t a_lane_off =
        (uint32_t)((wm * 64 + (lane & 15)) * AP + ((lane >> 4) * 8)) * 2u;
    const uint32_t b_lane_off =
        (uint32_t)((wn * 64 + (lane & 7) + ((lane >> 4) & 1) * 8) * AP
                   + (((lane >> 3) & 1) * 8)) * 2u;

    for (int t = 0; t < NT; ++t) {
        if (t + 1 < NT) {
            asm volatile("cp.async.wait_group 1;");
        } else {
            asm volatile("cp.async.wait_group 0;");
        }
        __syncthreads();
        if (t + 2 < NT) issue(t + 2, (t + 2) % 3);

        const uint32_t sa = sbase + (uint32_t)(t % 3) * STGH * 2u;
        const uint32_t aaddr = sa + a_lane_off;
        const uint32_t baddr = sa + ASTGH * 2u + b_lane_off;

#pragma unroll
        for (int ks = 0; ks < 4; ++ks) {
            uint32_t af[4][4], bf[4][4];
#pragma unroll
            for (int ms = 0; ms < 4; ms++)
                ldsm4(af[ms], aaddr + (uint32_t)(ms * 16 * AP + ks * 16) * 2u);
#pragma unroll
            for (int np = 0; np < 4; np++)
                ldsm4(bf[np], baddr + (uint32_t)(np * 16 * AP + ks * 16) * 2u);
#pragma unroll
            for (int ms = 0; ms < 4; ms++)
#pragma unroll
                for (int np = 0; np < 4; np++) {
                    mma_f16(acc[ms][np * 2], af[ms], bf[np]);
                    mma_f16(acc[ms][np * 2 + 1], af[ms], bf[np] + 2);
                }
        }
    }

    float2 bv[8];
#pragma unroll
    for (int ns = 0; ns < 8; ns++) {
        const int col = n0 + wn * 64 + ns * 8 + 2 * (lane & 3);
        bv[ns] = *(const float2*)(bias + col);
    }

    if (half_out) {
        __half* C = (__half*)Cout;
#pragma unroll
        for (int ms = 0; ms < 4; ms++) {
            const int row0 = m0 + wm * 64 + ms * 16 + (lane >> 2);
#pragma unroll
            for (int ns = 0; ns < 8; ns++) {
                const int col = n0 + wn * 64 + ns * 8 + 2 * (lane & 3);
                __half2 v0 = __floats2half2_rn((acc[ms][ns][0] + bv[ns].x) * scale,
                                               (acc[ms][ns][1] + bv[ns].y) * scale);
                __half2 v1 = __floats2half2_rn((acc[ms][ns][2] + bv[ns].x) * scale,
                                               (acc[ms][ns][3] + bv[ns].y) * scale);
                *(__half2*)(C + (size_t)row0 * GN + col) = v0;
                *(__half2*)(C + (size_t)(row0 + 8) * GN + col) = v1;
            }
        }
    } else {
        float* C = (float*)Cout;
#pragma unroll
        for (int ms = 0; ms < 4; ms++) {
            const int row0 = m0 + wm * 64 + ms * 16 + (lane >> 2);
#pragma unroll
            for (int ns = 0; ns < 8; ns++) {
                const int col = n0 + wn * 64 + ns * 8 + 2 * (lane & 3);
                float2 v0 = make_float2(acc[ms][ns][0] + bv[ns].x,
                                        acc[ms][ns][1] + bv[ns].y);
                float2 v1 = make_float2(acc[ms][ns][2] + bv[ns].x,
                                        acc[ms][ns][3] + bv[ns].y);
                *(float2*)(C + (size_t)row0 * GN + col) = v0;
                *(float2*)(C + (size_t)(row0 + 8) * GN + col) = v1;
            }
        }
    }
}

__global__ __launch_bounds__(GEMM_THREADS, 2)
void gemm_qkv(const __half* __restrict__ xq, const __half* __restrict__ xk,
              const __half* __restrict__ xv,
              const __half* __restrict__ wq, const __half* __restrict__ wk,
              const __half* __restrict__ wv,
              const float* __restrict__ bq, const float* __restrict__ bk,
              const float* __restrict__ bv,
              __half* __restrict__ pq, __half* __restrict__ pk,
              __half* __restrict__ pv)
{
    const int z = blockIdx.z;
    const __half* A = (z == 0) ? xq : (z == 1) ? xk : xv;
    const __half* W = (z == 0) ? wq : (z == 1) ? wk : wv;
    const float* bias = (z == 0) ? bq : (z == 1) ? bk : bv;
    __half* C = (z == 0) ? pq : (z == 1) ? pk : pv;
    const float scale = (z == 0) ? (ATT_SCALE * LOG2E) : 1.0f;
    gemm_core(A, W, bias, C, scale, 1, blockIdx.x, blockIdx.y);
}

__global__ __launch_bounds__(GEMM_THREADS, 2)
void gemm_one(const __half* __restrict__ A, const __half* __restrict__ W,
              const float* __restrict__ bias, void* __restrict__ Cout,
              float scale, int half_out)
{
    gemm_core(A, W, bias, Cout, scale, half_out, blockIdx.x, blockIdx.y);
}

// ===========================================================================
// fp16 flash attention v5: 64-q-row CTAs, 2 CTAs/SM, ex2.approx.f16x2 softmax
// (half the MUFU ops; result doubles as the PV A-fragment).
// ===========================================================================
#define FQ 64
#define FK 64
#define FP 136
#define QTILE_H (FQ * FP)
#define KTILE_H (FK * FP)
#define FLASH_SMEM ((QTILE_H + 4 * KTILE_H) * 2)   // 87040 B
#define FLASH_THREADS 128
#define NQT (SEQ / FQ)                 // 32

__global__ __launch_bounds__(FLASH_THREADS, 2)
void flash_tc(const __half* __restrict__ Q, const __half* __restrict__ K,
              const __half* __restrict__ V, __half* __restrict__ O)
{
    extern __shared__ __half fsmh[];

    const int qt = NQT - 1 - blockIdx.x;   // heavy tiles first
    const int h = blockIdx.y;
    const int b = blockIdx.z;
    const int q0 = qt * FQ;
    const size_t headoff = (size_t)b * SEQ * DMODEL + (size_t)h * HDIM;
    const __half* Qb = Q + headoff;
    const __half* Kb = K + headoff;
    const __half* Vb = V + headoff;

    const int tid = threadIdx.x;
    const int lane = tid & 31;
    const int warp = tid >> 5;
    const int g = lane >> 2;
    const int q4 = lane & 3;

    const uint32_t sQ = smem_u32(fsmh);
    const uint32_t sK0 = sQ + QTILE_H * 2u;
    const uint32_t sV0 = sQ + (QTILE_H + 2 * KTILE_H) * 2u;

#pragma unroll
    for (int i = 0; i < 8; ++i) {
        const int slot = tid + i * FLASH_THREADS;
        const int r = slot >> 4, c = slot & 15;
        cp16(sQ + (uint32_t)(r * FP + c * 8) * 2u,
             Qb + (size_t)(q0 + r) * DMODEL + c * 8);
    }

    auto issue_kv = [&](int kt) {
        const int buf = kt & 1;
        const int k0 = kt * FK;
        const uint32_t dK = sK0 + (uint32_t)buf * KTILE_H * 2u;
        const uint32_t dV = sV0 + (uint32_t)buf * KTILE_H * 2u;
#pragma unroll
        for (int i = 0; i < 8; ++i) {
            const int slot = tid + i * FLASH_THREADS;
            const int r = slot >> 4, c = slot & 15;
            cp16(dK + (uint32_t)(r * FP + c * 8) * 2u,
                 Kb + (size_t)(k0 + r) * DMODEL + c * 8);
            cp16(dV + (uint32_t)(r * FP + c * 8) * 2u,
                 Vb + (size_t)(k0 + r) * DMODEL + c * 8);
        }
        asm volatile("cp.async.commit_group;");
    };

    issue_kv(0);
    if (qt > 0) issue_kv(1);

    float m0 = -INFINITY, m1 = -INFINITY, l0 = 0.0f, l1 = 0.0f;
    float acco[16][4];
#pragma unroll
    for (int j = 0; j < 16; j++)
#pragma unroll
        for (int r = 0; r < 4; r++) acco[j][r] = 0.0f;

    const int ar = warp * 16 + g;

    const uint32_t qa_off =
        (uint32_t)((warp * 16 + (lane & 15)) * FP + ((lane >> 4) * 8)) * 2u;
    const uint32_t kb4_off =
        (uint32_t)(((lane & 7) + ((lane >> 4) & 1) * 8) * FP
                   + (((lane >> 3) & 1) * 8)) * 2u;
    const uint32_t vt4_off =
        (uint32_t)(((lane & 7) + ((lane >> 3) & 1) * 8) * FP
                   + ((lane >> 4) * 8)) * 2u;

    uint32_t qf[8][4];
    bool qloaded = false;

    for (int kt = 0; kt <= qt; ++kt) {
        const int buf = kt & 1;
        const uint32_t sKc = sK0 + (uint32_t)buf * KTILE_H * 2u;
        const uint32_t sVc = sV0 + (uint32_t)buf * KTILE_H * 2u;

        if (kt < qt) {
            asm volatile("cp.async.wait_group 1;");
        } else {
            asm volatile("cp.async.wait_group 0;");
        }
        __syncthreads();

        if (!qloaded) {
#pragma unroll
            for (int ks = 0; ks < 8; ++ks)
                ldsm4(qf[ks], sQ + qa_off + (uint32_t)(ks * 16) * 2u);
            qloaded = true;
        }

        // ---- S = Q @ K^T : 16 q x 64 kv per warp (64 MMAs) ----
        float accs[8][4];
#pragma unroll
        for (int j = 0; j < 8; j++)
#pragma unroll
            for (int r = 0; r < 4; r++) accs[j][r] = 0.0f;

#pragma unroll
        for (int jp = 0; jp < 4; ++jp) {
#pragma unroll
            for (int ks = 0; ks < 8; ++ks) {
                uint32_t bb[4];
                ldsm4(bb, sKc + kb4_off + (uint32_t)(jp * 16 * FP + ks * 16) * 2u);
                mma_f16(accs[jp * 2], qf[ks], bb);
                mma_f16(accs[jp * 2 + 1], qf[ks], bb + 2);
            }
        }

        if (kt == qt) {
#pragma unroll
            for (int j = 0; j < 8; ++j) {
                const int c0 = j * 8 + 2 * q4;
                if (c0 > ar)          accs[j][0] = -1e30f;
                if (c0 + 1 > ar)      accs[j][1] = -1e30f;
                if (c0 > ar + 8)      accs[j][2] = -1e30f;
                if (c0 + 1 > ar + 8)  accs[j][3] = -1e30f;
            }
        }

        // ---- online softmax (exp2 domain, f16x2 MUFU) ----
        float mx0 = -INFINITY, mx1 = -INFINITY;
#pragma unroll
        for (int j = 0; j < 8; ++j) {
            mx0 = fmaxf(mx0, fmaxf(accs[j][0], accs[j][1]));
            mx1 = fmaxf(mx1, fmaxf(accs[j][2], accs[j][3]));
        }
        mx0 = fmaxf(mx0, __shfl_xor_sync(0xffffffffu, mx0, 1));
        mx0 = fmaxf(mx0, __shfl_xor_sync(0xffffffffu, mx0, 2));
        mx1 = fmaxf(mx1, __shfl_xor_sync(0xffffffffu, mx1, 1));
        mx1 = fmaxf(mx1, __shfl_xor_sync(0xffffffffu, mx1, 2));
        const float mn0 = fmaxf(m0, mx0);
        const float mn1 = fmaxf(m1, mx1);
        const float cr0 = exp2f(m0 - mn0);
        const float cr1 = exp2f(m1 - mn1);

        // P = exp2(S - m) as packed half2 (doubles as PV A-fragment words)
        uint32_t p01[8], p23[8];
        float s0 = 0.0f, s1 = 0.0f;
#pragma unroll
        for (int j = 0; j < 8; ++j) {
            p01[j] = ex2_h2(accs[j][0] - mn0, accs[j][1] - mn0);
            p23[j] = ex2_h2(accs[j][2] - mn1, accs[j][3] - mn1);
            float2 f0 = __half22float2(*(__half2*)&p01[j]);
            float2 f1 = __half22float2(*(__half2*)&p23[j]);
            s0 += f0.x + f0.y;
            s1 += f1.x + f1.y;
        }
        s0 += __shfl_xor_sync(0xffffffffu, s0, 1);
        s0 += __shfl_xor_sync(0xffffffffu, s0, 2);
        s1 += __shfl_xor_sync(0xffffffffu, s1, 1);
        s1 += __shfl_xor_sync(0xffffffffu, s1, 2);
        l0 = l0 * cr0 + s0;  m0 = mn0;
        l1 = l1 * cr1 + s1;  m1 = mn1;
#pragma unroll
        for (int j = 0; j < 16; ++j) {
            acco[j][0] *= cr0; acco[j][1] *= cr0;
            acco[j][2] *= cr1; acco[j][3] *= cr1;
        }

        // ---- O += P @ V : A-fragments come straight from ex2 output ----
#pragma unroll
        for (int t = 0; t < 4; ++t) {
            uint32_t a[4];
            a[0] = p01[2 * t];
            a[1] = p23[2 * t];
            a[2] = p01[2 * t + 1];
            a[3] = p23[2 * t + 1];
#pragma unroll
            for (int jp = 0; jp < 8; ++jp) {
                uint32_t bb[4];
                ldsm4t(bb, sVc + vt4_off + (uint32_t)(t * 16 * FP + jp * 16) * 2u);
                mma_f16(acco[jp * 2], a, bb);
                mma_f16(acco[jp * 2 + 1], a, bb + 2);
            }
        }

        __syncthreads();
        if (kt + 2 <= qt) issue_kv(kt + 2);
    }

    const float i0 = 1.0f / l0;
    const float i1 = 1.0f / l1;
#pragma unroll
    for (int j = 0; j < 16; ++j) {
        *(__half2*)(O + headoff + (size_t)(q0 + ar) * DMODEL + j * 8 + 2 * q4) =
            __floats2half2_rn(acco[j][0] * i0, acco[j][1] * i0);
        *(__half2*)(O + headoff + (size_t)(q0 + ar + 8) * DMODEL + j * 8 + 2 * q4) =
            __floats2half2_rn(acco[j][2] * i1, acco[j][3] * i1);
    }
}

// ---------------------------------------------------------------------------
extern "C" void kernel_launch(void* const* d_in, const int* in_sizes, int n_in,
                              void* d_out, int out_size)
{
    const float* query = (const float*)d_in[0];
    const float* key_i = (const float*)d_in[1];
    const float* value = (const float*)d_in[2];
    const float* Wq = (const float*)d_in[3];
    const float* bq = (const float*)d_in[4];
    const float* Wk = (const float*)d_in[5];
    const float* bk = (const float*)d_in[6];
    const float* Wv = (const float*)d_in[7];
    const float* bv = (const float*)d_in[8];
    const float* Wo = (const float*)d_in[9];
    const float* bo = (const float*)d_in[10];
    float* out = (float*)d_out;

    __half *xq, *xk, *xv, *wq, *wk, *wv, *wo, *pq, *pk, *pv, *pa;
    cudaGetSymbolAddress((void**)&xq, hx_q);
    cudaGetSymbolAddress((void**)&xk, hx_k);
    cudaGetSymbolAddress((void**)&xv, hx_v);
    cudaGetSymbolAddress((void**)&wq, hw_q);
    cudaGetSymbolAddress((void**)&wk, hw_k);
    cudaGetSymbolAddress((void**)&wv, hw_v);
    cudaGetSymbolAddress((void**)&wo, hw_o);
    cudaGetSymbolAddress((void**)&pq, h_q);
    cudaGetSymbolAddress((void**)&pk, h_k);
    cudaGetSymbolAddress((void**)&pv, h_v);
    cudaGetSymbolAddress((void**)&pa, h_a);

    const int act4 = (MROWS * DMODEL) / 4;    // 2,097,152 (divisible by 1024)
    const int w4 = (DMODEL * DMODEL) / 4;     // 1,048,576 (divisible by 1024)
    conv_act<<<dim3(act4 / 1024, 3), 256>>>(
        (const float4*)query, (const float4*)key_i, (const float4*)value,
        (uint2*)xq, (uint2*)xk, (uint2*)xv, act4);
    conv_w<<<dim3(w4 / 1024, 4), 256>>>(
        (const float4*)Wq, (const float4*)Wk, (const float4*)Wv,
        (const float4*)Wo, (uint2*)wq, (uint2*)wk, (uint2*)wv, (uint2*)wo, w4);

    cudaFuncSetAttribute(gemm_qkv, cudaFuncAttributeMaxDynamicSharedMemorySize,
                         GEMM_SMEM);
    cudaFuncSetAttribute(gemm_one, cudaFuncAttributeMaxDynamicSharedMemorySize,
                         GEMM_SMEM);

    gemm_qkv<<<dim3(GN / TBN, MROWS / TBM, 3), GEMM_THREADS, GEMM_SMEM>>>(
        xq, xk, xv, wq, wk, wv, bq, bk, bv, pq, pk, pv);

    cudaFuncSetAttribute(flash_tc, cudaFuncAttributeMaxDynamicSharedMemorySize,
                         FLASH_SMEM);
    const dim3 agrid(NQT, NHEAD, BATCH);   // 1024 CTAs
    flash_tc<<<agrid, FLASH_THREADS, FLASH_SMEM>>>(pq, pk, pv, pa);

    gemm_one<<<dim3(GN / TBN, MROWS / TBM), GEMM_THREADS, GEMM_SMEM>>>(
        pa, wo, bo, out, 1.0f, 0);
}

// round 13
// speedup vs baseline: 2.5831x; 1.0151x over previous
#include <cuda_runtime.h>
#include <cuda_fp16.h>
#include <math.h>
#include <stdint.h>

#define BATCH 2
#define SEQ 2048
#define DMODEL 2048
#define NHEAD 16
#define HDIM 128
#define MROWS (BATCH * SEQ)          // 4096
#define ATT_SCALE 0.08838834764831845f  // 1/sqrt(128)
#define LOG2E 1.4426950408889634f

// Scratch (device globals: allocation-free per harness rules)
__device__ __half hx_q[(size_t)MROWS * DMODEL];   // fp16 inputs
__device__ __half hx_k[(size_t)MROWS * DMODEL];
__device__ __half hx_v[(size_t)MROWS * DMODEL];
__device__ __half hw_q[(size_t)DMODEL * DMODEL];  // fp16 weights
__device__ __half hw_k[(size_t)DMODEL * DMODEL];
__device__ __half hw_v[(size_t)DMODEL * DMODEL];
__device__ __half hw_o[(size_t)DMODEL * DMODEL];
__device__ __half h_q[(size_t)MROWS * DMODEL];    // projected q (pre-scaled)
__device__ __half h_k[(size_t)MROWS * DMODEL];
__device__ __half h_v[(size_t)MROWS * DMODEL];
__device__ __half h_a[(size_t)MROWS * DMODEL];    // attention output

// ===========================================================================
// helpers
// ===========================================================================
__device__ __forceinline__ uint32_t smem_u32(const void* p) {
    uint32_t a;
    asm("{ .reg .u64 t; cvta.to.shared.u64 t, %1; cvt.u32.u64 %0, t; }"
        : "=r"(a) : "l"(p));
    return a;
}

__device__ __forceinline__ void cp16(uint32_t dst, const void* src) {
    asm volatile("cp.async.cg.shared.global [%0], [%1], 16;"
                 :: "r"(dst), "l"(src));
}

__device__ __forceinline__ void mma_f16(float* d, const uint32_t* a,
                                        const uint32_t* b)
{
    asm volatile(
        "mma.sync.aligned.m16n8k16.row.col.f32.f16.f16.f32 "
        "{%0,%1,%2,%3}, {%4,%5,%6,%7}, {%8,%9}, {%0,%1,%2,%3};"
        : "+f"(d[0]), "+f"(d[1]), "+f"(d[2]), "+f"(d[3])
        : "r"(a[0]), "r"(a[1]), "r"(a[2]), "r"(a[3]),
          "r"(b[0]), "r"(b[1]));
}

__device__ __forceinline__ void ldsm4(uint32_t* r, uint32_t a) {
    asm volatile("ldmatrix.sync.aligned.m8n8.x4.shared.b16 {%0,%1,%2,%3}, [%4];"
                 : "=r"(r[0]), "=r"(r[1]), "=r"(r[2]), "=r"(r[3]) : "r"(a));
}
__device__ __forceinline__ void ldsm4t(uint32_t* r, uint32_t a) {
    asm volatile("ldmatrix.sync.aligned.m8n8.x4.trans.shared.b16 {%0,%1,%2,%3}, [%4];"
                 : "=r"(r[0]), "=r"(r[1]), "=r"(r[2]), "=r"(r[3]) : "r"(a));
}

// exp2 on a packed pair of (fp32 -> fp16) values; result is an MMA A-frag word
__device__ __forceinline__ uint32_t ex2_h2(float x, float y) {
    __half2 hv = __floats2half2_rn(x, y);
    uint32_t u = *(uint32_t*)&hv;
    uint32_t r;
    asm("ex2.approx.f16x2 %0, %1;" : "=r"(r) : "r"(u));
    return r;
}

// ===========================================================================
// merged fp32 -> fp16 conversion passes (4 float4 per thread for MLP)
// ===========================================================================
__device__ __forceinline__ uint2 cvt4(float4 v) {
    union { __half2 h[2]; uint2 u; } p;
    p.h[0] = __floats2half2_rn(v.x, v.y);
    p.h[1] = __floats2half2_rn(v.z, v.w);
    return p.u;
}

__global__ void conv_act(const float4* __restrict__ q,
                         const float4* __restrict__ k,
                         const float4* __restrict__ v,
                         uint2* __restrict__ oq, uint2* __restrict__ ok,
                         uint2* __restrict__ ov, int n4)
{
    const float4* src = (blockIdx.y == 0) ? q : (blockIdx.y == 1) ? k : v;
    uint2* dst = (blockIdx.y == 0) ? oq : (blockIdx.y == 1) ? ok : ov;
    const int base = blockIdx.x * 1024 + threadIdx.x;
    float4 v0 = src[base];
    float4 v1 = src[base + 256];
    float4 v2 = src[base + 512];
    float4 v3 = src[base + 768];
    dst[base] = cvt4(v0);
    dst[base + 256] = cvt4(v1);
    dst[base + 512] = cvt4(v2);
    dst[base + 768] = cvt4(v3);
}

__global__ void conv_w(const float4* __restrict__ w0,
                       const float4* __restrict__ w1,
                       const float4* __restrict__ w2,
                       const float4* __restrict__ w3,
                       uint2* __restrict__ o0, uint2* __restrict__ o1,
                       uint2* __restrict__ o2, uint2* __restrict__ o3, int n4)
{
    const float4* src = (blockIdx.y == 0) ? w0 : (blockIdx.y == 1) ? w1
                      : (blockIdx.y == 2) ? w2 : w3;
    uint2* dst = (blockIdx.y == 0) ? o0 : (blockIdx.y == 1) ? o1
               : (blockIdx.y == 2) ? o2 : o3;
    const int base = blockIdx.x * 1024 + threadIdx.x;
    float4 v0 = src[base];
    float4 v1 = src[base + 256];
    float4 v2 = src[base + 512];
    float4 v3 = src[base + 768];
    dst[base] = cvt4(v0);
    dst[base + 256] = cvt4(v1);
    dst[base + 512] = cvt4(v2);
    dst[base + 768] = cvt4(v3);
}

// ===========================================================================
// fp16 mma.sync GEMM core v2: CTA 128x128, 128 threads, 4 warps (2x2 of
// 64x64), BK=64, 2-stage cp.async, register-light fragments -> 3 CTAs/SM.
// ===========================================================================
#define TBM 128
#define TBN 128
#define GK 2048
#define GN 2048
#define GBKH 64
#define AP 72
#define ASTGH (TBM * AP)
#define BSTGH (TBN * AP)
#define STGH (ASTGH + BSTGH)
#define GEMM_SMEM (2 * STGH * 2)      // 73728 B -> 3 CTAs/SM
#define NT (GK / GBKH)                // 32
#define GEMM_THREADS 128

__device__ __forceinline__ void gemm_core(
    const __half* __restrict__ A, const __half* __restrict__ W,
    const float* __restrict__ bias, void* __restrict__ Cout,
    float scale, int half_out, int bx, int by)
{
    extern __shared__ __half gsmh[];

    const int tid = threadIdx.x;
    const int lane = tid & 31;
    const int warp = tid >> 5;
    const int wm = warp & 1;
    const int wn = warp >> 1;
    const int m0 = by * TBM;
    const int n0 = bx * TBN;

    const uint32_t sbase = smem_u32(gsmh);
    const int cr = tid >> 3;
    const int cc = tid & 7;

    float acc[4][8][4];
#pragma unroll
    for (int i = 0; i < 4; i++)
#pragma unroll
        for (int j = 0; j < 8; j++)
#pragma unroll
            for (int r = 0; r < 4; r++) acc[i][j][r] = 0.0f;

    auto issue = [&](int t, int buf) {
        const __half* Ab = A + (size_t)m0 * GK + t * GBKH;
        const __half* Wb = W + (size_t)n0 * GK + t * GBKH;
        const uint32_t sa = sbase + (uint32_t)buf * STGH * 2u;
        const uint32_t sb = sa + ASTGH * 2u;
#pragma unroll
        for (int i = 0; i < 8; i++) {
            const int r = cr + i * 16;
            cp16(sa + (uint32_t)(r * AP + cc * 8) * 2u,
                 Ab + (size_t)r * GK + cc * 8);
            cp16(sb + (uint32_t)(r * AP + cc * 8) * 2u,
                 Wb + (size_t)r * GK + cc * 8);
        }
        asm volatile("cp.async.commit_group;");
    };

    issue(0, 0);

    const uint32_t a_lane_off =
        (uint32_t)((wm * 64 + (lane & 15)) * AP + ((lane >> 4) * 8)) * 2u;
    const uint32_t b_lane_off =
        (uint32_t)((wn * 64 + (lane & 7) + ((lane >> 4) & 1) * 8) * AP
                   + (((lane >> 3) & 1) * 8)) * 2u;

    for (int t = 0; t < NT; ++t) {
        if (t + 1 < NT) {
            issue(t + 1, (t + 1) & 1);
            asm volatile("cp.async.wait_group 1;");
        } else {
            asm volatile("cp.async.wait_group 0;");
        }
        __syncthreads();

        const uint32_t sa = sbase + (uint32_t)(t & 1) * STGH * 2u;
        const uint32_t aaddr = sa + a_lane_off;
        const uint32_t baddr = sa + ASTGH * 2u + b_lane_off;

#pragma unroll
        for (int ks = 0; ks < 4; ++ks) {
            uint32_t bf[4][4];
#pragma unroll
            for (int np = 0; np < 4; np++)
                ldsm4(bf[np], baddr + (uint32_t)(np * 16 * AP + ks * 16) * 2u);
#pragma unroll
            for (int ms = 0; ms < 4; ms++) {
                uint32_t af[4];
                ldsm4(af, aaddr + (uint32_t)(ms * 16 * AP + ks * 16) * 2u);
#pragma unroll
                for (int np = 0; np < 4; np++) {
                    mma_f16(acc[ms][np * 2], af, bf[np]);
                    mma_f16(acc[ms][np * 2 + 1], af, bf[np] + 2);
                }
            }
        }
        __syncthreads();   // all reads of buf (t&1) done before issue(t+2)
    }

    float2 bv[8];
#pragma unroll
    for (int ns = 0; ns < 8; ns++) {
        const int col = n0 + wn * 64 + ns * 8 + 2 * (lane & 3);
        bv[ns] = *(const float2*)(bias + col);
    }

    if (half_out) {
        __half* C = (__half*)Cout;
#pragma unroll
        for (int ms = 0; ms < 4; ms++) {
            const int row0 = m0 + wm * 64 + ms * 16 + (lane >> 2);
#pragma unroll
            for (int ns = 0; ns < 8; ns++) {
                const int col = n0 + wn * 64 + ns * 8 + 2 * (lane & 3);
                __half2 v0 = __floats2half2_rn((acc[ms][ns][0] + bv[ns].x) * scale,
                                               (acc[ms][ns][1] + bv[ns].y) * scale);
                __half2 v1 = __floats2half2_rn((acc[ms][ns][2] + bv[ns].x) * scale,
                                               (acc[ms][ns][3] + bv[ns].y) * scale);
                *(__half2*)(C + (size_t)row0 * GN + col) = v0;
                *(__half2*)(C + (size_t)(row0 + 8) * GN + col) = v1;
            }
        }
    } else {
        float* C = (float*)Cout;
#pragma unroll
        for (int ms = 0; ms < 4; ms++) {
            const int row0 = m0 + wm * 64 + ms * 16 + (lane >> 2);
#pragma unroll
            for (int ns = 0; ns < 8; ns++) {
                const int col = n0 + wn * 64 + ns * 8 + 2 * (lane & 3);
                float2 v0 = make_float2(acc[ms][ns][0] + bv[ns].x,
                                        acc[ms][ns][1] + bv[ns].y);
                float2 v1 = make_float2(acc[ms][ns][2] + bv[ns].x,
                                        acc[ms][ns][3] + bv[ns].y);
                *(float2*)(C + (size_t)row0 * GN + col) = v0;
                *(float2*)(C + (size_t)(row0 + 8) * GN + col) = v1;
            }
        }
    }
}

__global__ __launch_bounds__(GEMM_THREADS, 3)
void gemm_qkv(const __half* __restrict__ xq, const __half* __restrict__ xk,
              const __half* __restrict__ xv,
              const __half* __restrict__ wq, const __half* __restrict__ wk,
              const __half* __restrict__ wv,
              const float* __restrict__ bq, const float* __restrict__ bk,
              const float* __restrict__ bv,
              __half* __restrict__ pq, __half* __restrict__ pk,
              __half* __restrict__ pv)
{
    const int z = blockIdx.z;
    const __half* A = (z == 0) ? xq : (z == 1) ? xk : xv;
    const __half* W = (z == 0) ? wq : (z == 1) ? wk : wv;
    const float* bias = (z == 0) ? bq : (z == 1) ? bk : bv;
    __half* C = (z == 0) ? pq : (z == 1) ? pk : pv;
    const float scale = (z == 0) ? (ATT_SCALE * LOG2E) : 1.0f;
    gemm_core(A, W, bias, C, scale, 1, blockIdx.x, blockIdx.y);
}

__global__ __launch_bounds__(GEMM_THREADS, 3)
void gemm_one(const __half* __restrict__ A, const __half* __restrict__ W,
              const float* __restrict__ bias, void* __restrict__ Cout,
              float scale, int half_out)
{
    gemm_core(A, W, bias, Cout, scale, half_out, blockIdx.x, blockIdx.y);
}

// ===========================================================================
// fp16 flash attention v5 (unchanged from R12): 64-q-row CTAs, 2 CTAs/SM,
// ex2.approx.f16x2 softmax feeding PV A-fragments directly.
// ===========================================================================
#define FQ 64
#define FK 64
#define FP 136
#define QTILE_H (FQ * FP)
#define KTILE_H (FK * FP)
#define FLASH_SMEM ((QTILE_H + 4 * KTILE_H) * 2)   // 87040 B
#define FLASH_THREADS 128
#define NQT (SEQ / FQ)                 // 32

__global__ __launch_bounds__(FLASH_THREADS, 2)
void flash_tc(const __half* __restrict__ Q, const __half* __restrict__ K,
              const __half* __restrict__ V, __half* __restrict__ O)
{
    extern __shared__ __half fsmh[];

    const int qt = NQT - 1 - blockIdx.x;   // heavy tiles first
    const int h = blockIdx.y;
    const int b = blockIdx.z;
    const int q0 = qt * FQ;
    const size_t headoff = (size_t)b * SEQ * DMODEL + (size_t)h * HDIM;
    const __half* Qb = Q + headoff;
    const __half* Kb = K + headoff;
    const __half* Vb = V + headoff;

    const int tid = threadIdx.x;
    const int lane = tid & 31;
    const int warp = tid >> 5;
    const int g = lane >> 2;
    const int q4 = lane & 3;

    const uint32_t sQ = smem_u32(fsmh);
    const uint32_t sK0 = sQ + QTILE_H * 2u;
    const uint32_t sV0 = sQ + (QTILE_H + 2 * KTILE_H) * 2u;

#pragma unroll
    for (int i = 0; i < 8; ++i) {
        const int slot = tid + i * FLASH_THREADS;
        const int r = slot >> 4, c = slot & 15;
        cp16(sQ + (uint32_t)(r * FP + c * 8) * 2u,
             Qb + (size_t)(q0 + r) * DMODEL + c * 8);
    }

    auto issue_kv = [&](int kt) {
        const int buf = kt & 1;
        const int k0 = kt * FK;
        const uint32_t dK = sK0 + (uint32_t)buf * KTILE_H * 2u;
        const uint32_t dV = sV0 + (uint32_t)buf * KTILE_H * 2u;
#pragma unroll
        for (int i = 0; i < 8; ++i) {
            const int slot = tid + i * FLASH_THREADS;
            const int r = slot >> 4, c = slot & 15;
            cp16(dK + (uint32_t)(r * FP + c * 8) * 2u,
                 Kb + (size_t)(k0 + r) * DMODEL + c * 8);
            cp16(dV + (uint32_t)(r * FP + c * 8) * 2u,
                 Vb + (size_t)(k0 + r) * DMODEL + c * 8);
        }
        asm volatile("cp.async.commit_group;");
    };

    issue_kv(0);
    if (qt > 0) issue_kv(1);

    float m0 = -INFINITY, m1 = -INFINITY, l0 = 0.0f, l1 = 0.0f;
    float acco[16][4];
#pragma unroll
    for (int j = 0; j < 16; j++)
#pragma unroll
        for (int r = 0; r < 4; r++) acco[j][r] = 0.0f;

    const int ar = warp * 16 + g;

    const uint32_t qa_off =
        (uint32_t)((warp * 16 + (lane & 15)) * FP + ((lane >> 4) * 8)) * 2u;
    const uint32_t kb4_off =
        (uint32_t)(((lane & 7) + ((lane >> 4) & 1) * 8) * FP
                   + (((lane >> 3) & 1) * 8)) * 2u;
    const uint32_t vt4_off =
        (uint32_t)(((lane & 7) + ((lane >> 3) & 1) * 8) * FP
                   + ((lane >> 4) * 8)) * 2u;

    uint32_t qf[8][4];
    bool qloaded = false;

    for (int kt = 0; kt <= qt; ++kt) {
        const int buf = kt & 1;
        const uint32_t sKc = sK0 + (uint32_t)buf * KTILE_H * 2u;
        const uint32_t sVc = sV0 + (uint32_t)buf * KTILE_H * 2u;

        if (kt < qt) {
            asm volatile("cp.async.wait_group 1;");
        } else {
            asm volatile("cp.async.wait_group 0;");
        }
        __syncthreads();

        if (!qloaded) {
#pragma unroll
            for (int ks = 0; ks < 8; ++ks)
                ldsm4(qf[ks], sQ + qa_off + (uint32_t)(ks * 16) * 2u);
            qloaded = true;
        }

        // ---- S = Q @ K^T ----
        float accs[8][4];
#pragma unroll
        for (int j = 0; j < 8; j++)
#pragma unroll
            for (int r = 0; r < 4; r++) accs[j][r] = 0.0f;

#pragma unroll
        for (int jp = 0; jp < 4; ++jp) {
#pragma unroll
            for (int ks = 0; ks < 8; ++ks) {
                uint32_t bb[4];
                ldsm4(bb, sKc + kb4_off + (uint32_t)(jp * 16 * FP + ks * 16) * 2u);
                mma_f16(accs[jp * 2], qf[ks], bb);
                mma_f16(accs[jp * 2 + 1], qf[ks], bb + 2);
            }
        }

        if (kt == qt) {
#pragma unroll
            for (int j = 0; j < 8; ++j) {
                const int c0 = j * 8 + 2 * q4;
                if (c0 > ar)          accs[j][0] = -1e30f;
                if (c0 + 1 > ar)      accs[j][1] = -1e30f;
                if (c0 > ar + 8)      accs[j][2] = -1e30f;
                if (c0 + 1 > ar + 8)  accs[j][3] = -1e30f;
            }
        }

        // ---- online softmax (exp2 domain, f16x2 MUFU) ----
        float mx0 = -INFINITY, mx1 = -INFINITY;
#pragma unroll
        for (int j = 0; j < 8; ++j) {
            mx0 = fmaxf(mx0, fmaxf(accs[j][0], accs[j][1]));
            mx1 = fmaxf(mx1, fmaxf(accs[j][2], accs[j][3]));
        }
        mx0 = fmaxf(mx0, __shfl_xor_sync(0xffffffffu, mx0, 1));
        mx0 = fmaxf(mx0, __shfl_xor_sync(0xffffffffu, mx0, 2));
        mx1 = fmaxf(mx1, __shfl_xor_sync(0xffffffffu, mx1, 1));
        mx1 = fmaxf(mx1, __shfl_xor_sync(0xffffffffu, mx1, 2));
        const float mn0 = fmaxf(m0, mx0);
        const float mn1 = fmaxf(m1, mx1);
        const float cr0 = exp2f(m0 - mn0);
        const float cr1 = exp2f(m1 - mn1);

        uint32_t p01[8], p23[8];
        float s0 = 0.0f, s1 = 0.0f;
#pragma unroll
        for (int j = 0; j < 8; ++j) {
            p01[j] = ex2_h2(accs[j][0] - mn0, accs[j][1] - mn0);
            p23[j] = ex2_h2(accs[j][2] - mn1, accs[j][3] - mn1);
            float2 f0 = __half22float2(*(__half2*)&p01[j]);
            float2 f1 = __half22float2(*(__half2*)&p23[j]);
            s0 += f0.x + f0.y;
            s1 += f1.x + f1.y;
        }
        s0 += __shfl_xor_sync(0xffffffffu, s0, 1);
        s0 += __shfl_xor_sync(0xffffffffu, s0, 2);
        s1 += __shfl_xor_sync(0xffffffffu, s1, 1);
        s1 += __shfl_xor_sync(0xffffffffu, s1, 2);
        l0 = l0 * cr0 + s0;  m0 = mn0;
        l1 = l1 * cr1 + s1;  m1 = mn1;
#pragma unroll
        for (int j = 0; j < 16; ++j) {
            acco[j][0] *= cr0; acco[j][1] *= cr0;
            acco[j][2] *= cr1; acco[j][3] *= cr1;
        }

        // ---- O += P @ V ----
#pragma unroll
        for (int t = 0; t < 4; ++t) {
            uint32_t a[4];
            a[0] = p01[2 * t];
            a[1] = p23[2 * t];
            a[2] = p01[2 * t + 1];
            a[3] = p23[2 * t + 1];
#pragma unroll
            for (int jp = 0; jp < 8; ++jp) {
                uint32_t bb[4];
                ldsm4t(bb, sVc + vt4_off + (uint32_t)(t * 16 * FP + jp * 16) * 2u);
                mma_f16(acco[jp * 2], a, bb);
                mma_f16(acco[jp * 2 + 1], a, bb + 2);
            }
        }

        __syncthreads();
        if (kt + 2 <= qt) issue_kv(kt + 2);
    }

    const float i0 = 1.0f / l0;
    const float i1 = 1.0f / l1;
#pragma unroll
    for (int j = 0; j < 16; ++j) {
        *(__half2*)(O + headoff + (size_t)(q0 + ar) * DMODEL + j * 8 + 2 * q4) =
            __floats2half2_rn(acco[j][0] * i0, acco[j][1] * i0);
        *(__half2*)(O + headoff + (size_t)(q0 + ar + 8) * DMODEL + j * 8 + 2 * q4) =
            __floats2half2_rn(acco[j][2] * i1, acco[j][3] * i1);
    }
}

// ---------------------------------------------------------------------------
extern "C" void kernel_launch(void* const* d_in, const int* in_sizes, int n_in,
                              void* d_out, int out_size)
{
    const float* query = (const float*)d_in[0];
    const float* key_i = (const float*)d_in[1];
    const float* value = (const float*)d_in[2];
    const float* Wq = (const float*)d_in[3];
    const float* bq = (const float*)d_in[4];
    const float* Wk = (const float*)d_in[5];
    const float* bk = (const float*)d_in[6];
    const float* Wv = (const float*)d_in[7];
    const float* bv = (const float*)d_in[8];
    const float* Wo = (const float*)d_in[9];
    const float* bo = (const float*)d_in[10];
    float* out = (float*)d_out;

    __half *xq, *xk, *xv, *wq, *wk, *wv, *wo, *pq, *pk, *pv, *pa;
    cudaGetSymbolAddress((void**)&xq, hx_q);
    cudaGetSymbolAddress((void**)&xk, hx_k);
    cudaGetSymbolAddress((void**)&xv, hx_v);
    cudaGetSymbolAddress((void**)&wq, hw_q);
    cudaGetSymbolAddress((void**)&wk, hw_k);
    cudaGetSymbolAddress((void**)&wv, hw_v);
    cudaGetSymbolAddress((void**)&wo, hw_o);
    cudaGetSymbolAddress((void**)&pq, h_q);
    cudaGetSymbolAddress((void**)&pk, h_k);
    cudaGetSymbolAddress((void**)&pv, h_v);
    cudaGetSymbolAddress((void**)&pa, h_a);

    const int act4 = (MROWS * DMODEL) / 4;
    const int w4 = (DMODEL * DMODEL) / 4;
    conv_act<<<dim3(act4 / 1024, 3), 256>>>(
        (const float4*)query, (const float4*)key_i, (const float4*)value,
        (uint2*)xq, (uint2*)xk, (uint2*)xv, act4);
    conv_w<<<dim3(w4 / 1024, 4), 256>>>(
        (const float4*)Wq, (const float4*)Wk, (const float4*)Wv,
        (const float4*)Wo, (uint2*)wq, (uint2*)wk, (uint2*)wv, (uint2*)wo, w4);

    cudaFuncSetAttribute(gemm_qkv, cudaFuncAttributeMaxDynamicSharedMemorySize,
                         GEMM_SMEM);
    cudaFuncSetAttribute(gemm_one, cudaFuncAttributeMaxDynamicSharedMemorySize,
                         GEMM_SMEM);

    gemm_qkv<<<dim3(GN / TBN, MROWS / TBM, 3), GEMM_THREADS, GEMM_SMEM>>>(
        xq, xk, xv, wq, wk, wv, bq, bk, bv, pq, pk, pv);

    cudaFuncSetAttribute(flash_tc, cudaFuncAttributeMaxDynamicSharedMemorySize,
                         FLASH_SMEM);
    const dim3 agrid(NQT, NHEAD, BATCH);   // 1024 CTAs
    flash_tc<<<agrid, FLASH_THREADS, FLASH_SMEM>>>(pq, pk, pv, pa);

    gemm_one<<<dim3(GN / TBN, MROWS / TBM), GEMM_THREADS, GEMM_SMEM>>>(
        pa, wo, bo, out, 1.0f, 0);
}